// round 13
// baseline (speedup 1.0000x reference)
#include <cuda_runtime.h>
#include <cuda_bf16.h>
#include <cuda_fp16.h>
#include <math.h>
#include <stdint.h>

#define NN 100000
#define NN_PAD 100096
#define NPB (NN_PAD / 128)
#define EE 1600000
#define HID 128
#define NEG 0.01f
#define BN_EPS 1e-5f
#define L2_EPS 1e-12f
#define NPW 4   // nodes per warp in F=128 SpMM

// ------------------------- device scratch -------------------------
__device__ uint32_t g_Thalf[(size_t)NN_PAD * 256]; // [T0|T1|T2|T3] fp16 packed, 64 half2/seg
__device__ float g_H[(size_t)NN * 128];            // GEMM output (pre-activation)
__device__ float g_t0[NN * 4];                     // layer-1 bases, float4-padded rows
__device__ float g_t1[NN * 4];
__device__ float g_t2[NN * 4];
__device__ float g_t3[NN * 4];
__device__ float g_dinv[NN];
__device__ int   g_indeg[NN];
__device__ int   g_ptr[NN + 1];
__device__ int   g_fill[NN];
__device__ int   g_bsums[256];
__device__ int2  g_edge[EE];
__device__ float g_part[NPB * 256];
__device__ float g_scale[128];
__device__ float g_shift[128];
__device__ uint32_t g_Wfhi[3 * 512 * 64];
__device__ uint32_t g_Wflo[3 * 512 * 64];
__device__ int   g_is64;

// ------------------------- helpers -------------------------
__device__ __forceinline__ uint32_t smem_u32(const void* p) {
    uint32_t a;
    asm("{ .reg .u64 t; cvta.to.shared.u64 t, %1; cvt.u32.u64 %0, t; }" : "=r"(a) : "l"(p));
    return a;
}

__device__ __forceinline__ uint32_t packh2(float a, float b) {
    __half2 h = __floats2half2_rn(a, b);
    return *reinterpret_cast<uint32_t*>(&h);
}

__device__ __forceinline__ void split2h(float x0, float x1, uint32_t& hi, uint32_t& lo) {
    __half h0 = __float2half_rn(x0);
    __half h1 = __float2half_rn(x1);
    float r0 = x0 - __half2float(h0);
    float r1 = x1 - __half2float(h1);
    __half2 H; H.x = h0; H.y = h1;
    hi = *reinterpret_cast<uint32_t*>(&H);
    lo = packh2(r0, r1);
}

#define MMAF16(c, a, b0, b1) \
    asm volatile("mma.sync.aligned.m16n8k16.row.col.f32.f16.f16.f32 " \
        "{%0,%1,%2,%3}, {%4,%5,%6,%7}, {%8,%9}, {%0,%1,%2,%3};" \
        : "+f"((c)[0]), "+f"((c)[1]), "+f"((c)[2]), "+f"((c)[3]) \
        : "r"((a)[0]), "r"((a)[1]), "r"((a)[2]), "r"((a)[3]), "r"(b0), "r"(b1))

#define LDSM4(r0, r1, r2, r3, a) \
    asm volatile("ldmatrix.sync.aligned.m8n8.x4.shared.b16 {%0,%1,%2,%3}, [%4];" \
        : "=r"(r0), "=r"(r1), "=r"(r2), "=r"(r3) : "r"(a))

#define LDSM4T(r0, r1, r2, r3, a) \
    asm volatile("ldmatrix.sync.aligned.m8n8.x4.trans.shared.b16 {%0,%1,%2,%3}, [%4];" \
        : "=r"(r0), "=r"(r1), "=r"(r2), "=r"(r3) : "r"(a))

__device__ __forceinline__ void cp16(uint32_t sdst, const void* gsrc) {
    asm volatile("cp.async.ca.shared.global [%0], [%1], 16;" :: "r"(sdst), "l"(gsrc) : "memory");
}

__device__ __forceinline__ void acc4(float* acc, uint2 v, float w) {
    float2 f0 = __half22float2(*reinterpret_cast<__half2*>(&v.x));
    float2 f1 = __half22float2(*reinterpret_cast<__half2*>(&v.y));
    acc[0] = fmaf(w, f0.x, acc[0]);
    acc[1] = fmaf(w, f0.y, acc[1]);
    acc[2] = fmaf(w, f1.x, acc[2]);
    acc[3] = fmaf(w, f1.y, acc[3]);
}

__device__ __forceinline__ float apply_act(float v, int act) {
    return act ? fmaxf(v, 0.0f) : (v >= 0.0f ? v : NEG * v);
}

// ------------------------- edge helpers -------------------------
__device__ __forceinline__ void load_edge(const void* ei, int E, int e, int& s, int& d) {
    if (g_is64) {
        const long long* p = (const long long*)ei;
        s = (int)p[e];
        d = (int)p[(size_t)E + e];
    } else {
        const int* p = (const int*)ei;
        s = p[e];
        d = p[E + e];
    }
}

// ------------------------- setup kernels -------------------------
__global__ void k_detect(const int* ei32) {
    if (threadIdx.x == 0 && blockIdx.x == 0) {
        int is64 = 1;
        for (int i = 0; i < 32; i++) {
            if (ei32[2 * i + 1] != 0) { is64 = 0; break; }
        }
        g_is64 = is64;
    }
}

// zero indeg + copy x into padded t0
__global__ void k_init(const float* __restrict__ x) {
    int i = blockIdx.x * blockDim.x + threadIdx.x;
    if (i < NN) {
        g_indeg[i] = 0;
        float4 v;
        v.x = x[3 * i];
        v.y = x[3 * i + 1];
        v.z = x[3 * i + 2];
        v.w = 0.0f;
        *(float4*)&g_t0[4 * i] = v;
    }
}

// symmetrized graph: in-degree == out-degree, count dst only
__global__ void k_count(const void* ei, int E) {
    int e = blockIdx.x * blockDim.x + threadIdx.x;
    if (e < E) {
        int s, d;
        load_edge(ei, E, e, s, d);
        atomicAdd(&g_indeg[d], 1);
    }
}

__global__ void k_dinv() {
    int i = blockIdx.x * blockDim.x + threadIdx.x;
    if (i < NN) {
        float dg = (float)g_indeg[i];
        g_dinv[i] = (dg > 0.0f) ? rsqrtf(fmaxf(dg, 1.0f)) : 0.0f;
    }
}

__global__ void k_scan1() {
    __shared__ int sh[512];
    int gid = blockIdx.x * 512 + threadIdx.x;
    int v = (gid < NN) ? g_indeg[gid] : 0;
    sh[threadIdx.x] = v;
    __syncthreads();
    for (int off = 1; off < 512; off <<= 1) {
        int t = (threadIdx.x >= off) ? sh[threadIdx.x - off] : 0;
        __syncthreads();
        sh[threadIdx.x] += t;
        __syncthreads();
    }
    if (gid <= NN) g_ptr[gid] = sh[threadIdx.x] - v;
    if (threadIdx.x == 511) g_bsums[blockIdx.x] = sh[511];
}

__global__ void k_scan2(int nb) {
    if (threadIdx.x == 0 && blockIdx.x == 0) {
        int acc = 0;
        for (int i = 0; i < nb; i++) { int t = g_bsums[i]; g_bsums[i] = acc; acc += t; }
    }
}

__global__ void k_scan3() {
    int gid = blockIdx.x * 512 + threadIdx.x;
    if (gid <= NN) {
        int p = g_ptr[gid] + g_bsums[blockIdx.x];
        g_ptr[gid] = p;
        if (gid < NN) g_fill[gid] = p;
    }
}

__global__ void k_scatter(const void* ei, int E) {
    int e = blockIdx.x * blockDim.x + threadIdx.x;
    if (e < E) {
        int s, d;
        load_edge(ei, E, e, s, d);
        float w = -(g_dinv[s] * g_dinv[d]);
        int pos = atomicAdd(&g_fill[d], 1);
        g_edge[pos] = make_int2(s, __float_as_int(w));
    }
}

// ------------------------- layer-1 sparse (F=3, float4 rows) -------------------------
__global__ void k_spmm3(int xc, int yc, int subc) {
    int i = blockIdx.x * blockDim.x + threadIdx.x;
    if (i >= NN) return;
    const float4* X = (const float4*)((xc == 0) ? g_t0 : (xc == 1) ? g_t1 : (xc == 2) ? g_t2 : g_t3);
    float4*       Y = (float4*)((yc == 1) ? g_t1 : (yc == 2) ? g_t2 : g_t3);
    int b = g_ptr[i], en = g_ptr[i + 1];
    float a0 = 0, a1 = 0, a2 = 0;
    int e = b;
    for (; e + 4 <= en; e += 4) {
        int2 e0 = __ldg(&g_edge[e]);
        int2 e1 = __ldg(&g_edge[e + 1]);
        int2 e2 = __ldg(&g_edge[e + 2]);
        int2 e3 = __ldg(&g_edge[e + 3]);
        float4 v0 = __ldg(&X[e0.x]);
        float4 v1 = __ldg(&X[e1.x]);
        float4 v2 = __ldg(&X[e2.x]);
        float4 v3 = __ldg(&X[e3.x]);
        float w0 = __int_as_float(e0.y), w1 = __int_as_float(e1.y);
        float w2 = __int_as_float(e2.y), w3 = __int_as_float(e3.y);
        a0 = fmaf(w0, v0.x, a0); a1 = fmaf(w0, v0.y, a1); a2 = fmaf(w0, v0.z, a2);
        a0 = fmaf(w1, v1.x, a0); a1 = fmaf(w1, v1.y, a1); a2 = fmaf(w1, v1.z, a2);
        a0 = fmaf(w2, v2.x, a0); a1 = fmaf(w2, v2.y, a1); a2 = fmaf(w2, v2.z, a2);
        a0 = fmaf(w3, v3.x, a0); a1 = fmaf(w3, v3.y, a1); a2 = fmaf(w3, v3.z, a2);
    }
    for (; e < en; e++) {
        int2 ed = __ldg(&g_edge[e]);
        float ww = __int_as_float(ed.y);
        float4 v = __ldg(&X[ed.x]);
        a0 = fmaf(ww, v.x, a0);
        a1 = fmaf(ww, v.y, a1);
        a2 = fmaf(ww, v.z, a2);
    }
    float4 o;
    if (subc < 0) {
        o = make_float4(a0, a1, a2, 0.0f);
    } else {
        const float4* S = (const float4*)((subc == 0) ? g_t0 : (subc == 1) ? g_t1 : (subc == 2) ? g_t2 : g_t3);
        float4 s = S[i];
        o = make_float4(2.0f * a0 - s.x, 2.0f * a1 - s.y, 2.0f * a2 - s.z, 0.0f);
    }
    Y[i] = o;
}

// ------------------------- F=128 SpMM: warp handles NPW consecutive nodes -------------------
__global__ void __launch_bounds__(256) k_spmm128w(int xseg, int yseg, int subseg) {
    int node0 = (blockIdx.x * 8 + (threadIdx.x >> 5)) * NPW;
    int lane = threadIdx.x & 31;
    const uint2* Xb = (const uint2*)g_Thalf;       // row = 128 uint2
    const uint32_t xo = xseg * 32 + lane;

    for (int q = 0; q < NPW; q++) {
        int node = node0 + q;
        if (node >= NN) return;
        int b = g_ptr[node], en = g_ptr[node + 1];
        float acc[4] = {0, 0, 0, 0};
        int e = b;
        for (; e + 4 <= en; e += 4) {
            int2 e0 = __ldg(&g_edge[e]);
            int2 e1 = __ldg(&g_edge[e + 1]);
            int2 e2 = __ldg(&g_edge[e + 2]);
            int2 e3 = __ldg(&g_edge[e + 3]);
            uint2 v0 = __ldg(&Xb[(size_t)e0.x * 128 + xo]);
            uint2 v1 = __ldg(&Xb[(size_t)e1.x * 128 + xo]);
            uint2 v2 = __ldg(&Xb[(size_t)e2.x * 128 + xo]);
            uint2 v3 = __ldg(&Xb[(size_t)e3.x * 128 + xo]);
            acc4(acc, v0, __int_as_float(e0.y));
            acc4(acc, v1, __int_as_float(e1.y));
            acc4(acc, v2, __int_as_float(e2.y));
            acc4(acc, v3, __int_as_float(e3.y));
        }
        for (; e < en; e++) {
            int2 ed = __ldg(&g_edge[e]);
            uint2 v = __ldg(&Xb[(size_t)ed.x * 128 + xo]);
            acc4(acc, v, __int_as_float(ed.y));
        }

        if (subseg >= 0) {
            uint2 s = __ldg((const uint2*)g_Thalf + (size_t)node * 128 + subseg * 32 + lane);
            float2 s0 = __half22float2(*reinterpret_cast<__half2*>(&s.x));
            float2 s1 = __half22float2(*reinterpret_cast<__half2*>(&s.y));
            acc[0] = 2.0f * acc[0] - s0.x;
            acc[1] = 2.0f * acc[1] - s0.y;
            acc[2] = 2.0f * acc[2] - s1.x;
            acc[3] = 2.0f * acc[3] - s1.y;
        }
        uint2 o;
        o.x = packh2(acc[0], acc[1]);
        o.y = packh2(acc[2], acc[3]);
        *((uint2*)g_Thalf + (size_t)node * 128 + yseg * 32 + lane) = o;
    }
}

// ------------------------- layer-1 GEMM (12 x 128) -------------------------
__global__ void __launch_bounds__(256) k_gemm1(const float* __restrict__ W1,
                                               const float* __restrict__ b1) {
    __shared__ float shW[12 * 128];
    __shared__ float shT[32 * 12];
    int tid = threadIdx.x;
    for (int i = tid; i < 1536; i += 256) shW[i] = W1[i];
    int r0 = blockIdx.x * 32;
    for (int i = tid; i < 384; i += 256) {
        int r = i / 12, j = i % 12;
        int k = j / 3, d = j % 3;
        int gr = r0 + r;
        float v = 0.0f;
        if (gr < NN) {
            const float* src = (k == 0) ? g_t0 : (k == 1) ? g_t1 : (k == 2) ? g_t2 : g_t3;
            v = src[gr * 4 + d];
        }
        shT[i] = v;
    }
    __syncthreads();
    int r = tid >> 3;
    int c0 = (tid & 7) * 16;
    int gr = r0 + r;
    if (gr < NN) {
        #pragma unroll
        for (int c = c0; c < c0 + 16; c++) {
            float acc = b1[c];
            #pragma unroll
            for (int j = 0; j < 12; j++) acc = fmaf(shT[r * 12 + j], shW[j * 128 + c], acc);
            g_H[(size_t)gr * 128 + c] = acc;
        }
    }
}

// ------------------------- weight prep -------------------------
__global__ void k_prepw(const float* __restrict__ W, int widx) {
    int i = blockIdx.x * 256 + threadIdx.x;
    if (i < 512 * 64) {
        int k = i >> 6, np = i & 63;
        float x0 = W[k * 128 + 2 * np];
        float x1 = W[k * 128 + 2 * np + 1];
        uint32_t hi, lo;
        split2h(x0, x1, hi, lo);
        g_Wfhi[widx * 512 * 64 + i] = hi;
        g_Wflo[widx * 512 * 64 + i] = lo;
    }
}

// ------------------------- fp16 2-term ldmatrix GEMM, 3-stage pipeline, fused BN stats ----
#define AST 20
#define BSTU 68
#define A_UINTS (128 * AST)
#define B_UINTS (32 * BSTU)
#define STAGE_UINTS (A_UINTS + 2 * B_UINTS)
#define SMEM_GEMM (3 * STAGE_UINTS * 4)

__global__ void __launch_bounds__(256, 2) k_gemm_f16(const float* __restrict__ bias,
                                                     int widx, int act) {
    extern __shared__ uint32_t sm[];
    const int tid = threadIdx.x;
    const int lane = tid & 31;
    const int wid = tid >> 5;
    const int wm = wid & 3;
    const int wn = wid >> 2;
    const int lk = lane & 3;
    const int lr = lane >> 2;
    const int row0 = blockIdx.x * 128;
    const uint32_t sbase = smem_u32(sm);
    const uint32_t* Whi = g_Wfhi + widx * 512 * 64;
    const uint32_t* Wlo = g_Wflo + widx * 512 * 64;

    float acc[2][8][4];
    #pragma unroll
    for (int mt = 0; mt < 2; mt++)
        #pragma unroll
        for (int nt = 0; nt < 8; nt++)
            #pragma unroll
            for (int q = 0; q < 4; q++) acc[mt][nt][q] = 0.0f;

    const int laneRow = lane & 15;
    const int laneHi = lane >> 4;
    const uint32_t aLaneOff = (uint32_t)((wm * 32 + laneRow) * 80 + laneHi * 16);
    const uint32_t bLaneOff = (uint32_t)(laneRow * 272 + (wn * 64 + laneHi * 8) * 2);

    auto issue = [&](int c, int stage) {
        uint32_t Ab  = sbase + stage * STAGE_UINTS * 4;
        uint32_t Bhb = Ab + A_UINTS * 4;
        uint32_t Blb = Bhb + B_UINTS * 4;
        int auoff = (c >> 2) * 64 + (c & 3) * 16;
        #pragma unroll
        for (int j = 0; j < 2; j++) {
            int q = tid * 2 + j;
            int r = q >> 2, s4 = (q & 3) * 4;
            cp16(Ab + (r * AST + s4) * 4,
                 g_Thalf + (size_t)(row0 + r) * 256 + auoff + s4);
        }
        int kb = c * 32;
        #pragma unroll
        for (int j = 0; j < 2; j++) {
            int q = tid * 2 + j;
            int kr = q >> 4, n4 = (q & 15) * 4;
            cp16(Bhb + (kr * BSTU + n4) * 4, Whi + (kb + kr) * 64 + n4);
            cp16(Blb + (kr * BSTU + n4) * 4, Wlo + (kb + kr) * 64 + n4);
        }
        asm volatile("cp.async.commit_group;" ::: "memory");
    };

    issue(0, 0);
    issue(1, 1);

    for (int c = 0; c < 16; c++) {
        asm volatile("cp.async.wait_group 1;" ::: "memory");
        __syncthreads();
        if (c + 2 < 16)
            issue(c + 2, (c + 2) % 3);
        {
            uint32_t Ab = sbase + (c % 3) * STAGE_UINTS * 4;
            uint32_t Bb = Ab + A_UINTS * 4;
            #pragma unroll
            for (int ks = 0; ks < 2; ks++) {
                uint32_t a[2][4];
                #pragma unroll
                for (int mt = 0; mt < 2; mt++) {
                    uint32_t addr = Ab + aLaneOff + (uint32_t)(mt * 16 * 80 + ks * 32);
                    LDSM4(a[mt][0], a[mt][1], a[mt][2], a[mt][3], addr);
                }
                #pragma unroll
                for (int ntp = 0; ntp < 4; ntp++) {
                    uint32_t baddr = Bb + bLaneOff + (uint32_t)(ks * 16 * 272 + ntp * 32);
                    uint32_t h0, h1, h2, h3;
                    LDSM4T(h0, h1, h2, h3, baddr);
                    MMAF16(acc[0][2 * ntp],     a[0], h0, h1);
                    MMAF16(acc[1][2 * ntp],     a[1], h0, h1);
                    MMAF16(acc[0][2 * ntp + 1], a[0], h2, h3);
                    MMAF16(acc[1][2 * ntp + 1], a[1], h2, h3);
                    uint32_t l0, l1, l2, l3;
                    LDSM4T(l0, l1, l2, l3, baddr + B_UINTS * 4);
                    MMAF16(acc[0][2 * ntp],     a[0], l0, l1);
                    MMAF16(acc[1][2 * ntp],     a[1], l0, l1);
                    MMAF16(acc[0][2 * ntp + 1], a[0], l2, l3);
                    MMAF16(acc[1][2 * ntp + 1], a[1], l2, l3);
                }
            }
        }
        __syncthreads();
    }

    const int r1b = row0 + wm * 32 + lr;
    #pragma unroll
    for (int mt = 0; mt < 2; mt++) {
        int r1 = r1b + mt * 16;
        int r2 = r1 + 8;
        #pragma unroll
        for (int nt = 0; nt < 8; nt++) {
            int col = wn * 64 + nt * 8 + 2 * lk;
            float2 bs = *(const float2*)&bias[col];
            acc[mt][nt][0] += bs.x; acc[mt][nt][1] += bs.y;
            acc[mt][nt][2] += bs.x; acc[mt][nt][3] += bs.y;
            if (r1 < NN)
                *(float2*)&g_H[(size_t)r1 * 128 + col] = make_float2(acc[mt][nt][0], acc[mt][nt][1]);
            if (r2 < NN)
                *(float2*)&g_H[(size_t)r2 * 128 + col] = make_float2(acc[mt][nt][2], acc[mt][nt][3]);
        }
    }

    if (act >= 0) {
        float* sred = (float*)sm;
        __syncthreads();
        #pragma unroll
        for (int nt = 0; nt < 8; nt++) {
            float s0 = 0, s1 = 0, q0 = 0, q1 = 0;
            #pragma unroll
            for (int mt = 0; mt < 2; mt++) {
                int r1 = r1b + mt * 16;
                int r2 = r1 + 8;
                if (r1 < NN) {
                    float v0 = apply_act(acc[mt][nt][0], act);
                    float v1 = apply_act(acc[mt][nt][1], act);
                    s0 += v0; q0 = fmaf(v0, v0, q0);
                    s1 += v1; q1 = fmaf(v1, v1, q1);
                }
                if (r2 < NN) {
                    float v0 = apply_act(acc[mt][nt][2], act);
                    float v1 = apply_act(acc[mt][nt][3], act);
                    s0 += v0; q0 = fmaf(v0, v0, q0);
                    s1 += v1; q1 = fmaf(v1, v1, q1);
                }
            }
            #pragma unroll
            for (int o = 4; o < 32; o <<= 1) {
                s0 += __shfl_xor_sync(0xFFFFFFFFu, s0, o);
                s1 += __shfl_xor_sync(0xFFFFFFFFu, s1, o);
                q0 += __shfl_xor_sync(0xFFFFFFFFu, q0, o);
                q1 += __shfl_xor_sync(0xFFFFFFFFu, q1, o);
            }
            if (lr == 0) {
                int col = wn * 64 + nt * 8 + 2 * lk;
                sred[wm * 256 + col] = s0;
                sred[wm * 256 + col + 1] = s1;
                sred[wm * 256 + 128 + col] = q0;
                sred[wm * 256 + 128 + col + 1] = q1;
            }
        }
        __syncthreads();
        g_part[blockIdx.x * 256 + tid] =
            sred[tid] + sred[256 + tid] + sred[512 + tid] + sred[768 + tid];
    }
}

// ------------------------- layer-1 column stats (strided) -------------------------
__global__ void __launch_bounds__(128) k_colstat1(int act) {
    int c = threadIdx.x;
    float s = 0.0f, s2 = 0.0f;
    for (int r = blockIdx.x; r < NN; r += NPB) {
        float v = g_H[(size_t)r * 128 + c];
        v = apply_act(v, act);
        s += v;
        s2 = fmaf(v, v, s2);
    }
    g_part[blockIdx.x * 256 + c] = s;
    g_part[blockIdx.x * 256 + 128 + c] = s2;
}

// ------------------------- BN scale/shift from partials -------------------------
__global__ void __launch_bounds__(128) k_colstat2(int nb,
                                                  const float* __restrict__ gamma,
                                                  const float* __restrict__ beta) {
    int c = threadIdx.x;
    float s = 0.0f, s2 = 0.0f;
    for (int b = 0; b < nb; b++) {
        s += g_part[b * 256 + c];
        s2 += g_part[b * 256 + 128 + c];
    }
    float mu = s / (float)NN;
    float var = s2 / (float)NN - mu * mu;
    float sc = gamma[c] * rsqrtf(var + BN_EPS);
    g_scale[c] = sc;
    g_shift[c] = beta[c] - mu * sc;
}

__global__ void __launch_bounds__(256) k_bnapply(int act) {
    int idx = blockIdx.x * blockDim.x + threadIdx.x;
    if (idx < NN * 64) {
        int p = idx & 63;
        int r = idx >> 6;
        int c = p * 2;
        float2 h = *(const float2*)&g_H[(size_t)r * 128 + c];
        float v0 = fmaf(apply_act(h.x, act), g_scale[c],     g_shift[c]);
        float v1 = fmaf(apply_act(h.y, act), g_scale[c + 1], g_shift[c + 1]);
        g_Thalf[(size_t)r * 256 + p] = packh2(v0, v1);
    }
}

// ------------------------- final: L2 norm + head -------------------------
__global__ void __launch_bounds__(256) k_final(const float* __restrict__ Wrep,
                                               const float* __restrict__ brep,
                                               float* __restrict__ out) {
    __shared__ float shW[384];
    int tid = threadIdx.x;
    for (int i = tid; i < 384; i += 256) shW[i] = Wrep[i];
    __syncthreads();
    int node = blockIdx.x * 8 + (tid >> 5);
    int lane = tid & 31;
    if (node >= NN) return;
    float4 h = *(const float4*)&g_H[(size_t)node * 128 + lane * 4];
    float hv[4] = {h.x, h.y, h.z, h.w};
    float ss = 0.0f, p0 = 0.0f, p1 = 0.0f, p2 = 0.0f;
    #pragma unroll
    for (int q = 0; q < 4; q++) {
        int f = lane * 4 + q;
        ss = fmaf(hv[q], hv[q], ss);
        p0 = fmaf(hv[q], shW[f * 3 + 0], p0);
        p1 = fmaf(hv[q], shW[f * 3 + 1], p1);
        p2 = fmaf(hv[q], shW[f * 3 + 2], p2);
    }
    #pragma unroll
    for (int o = 16; o > 0; o >>= 1) {
        ss += __shfl_xor_sync(0xFFFFFFFFu, ss, o);
        p0 += __shfl_xor_sync(0xFFFFFFFFu, p0, o);
        p1 += __shfl_xor_sync(0xFFFFFFFFu, p1, o);
        p2 += __shfl_xor_sync(0xFFFFFFFFu, p2, o);
    }
    if (lane == 0) {
        float inv = 1.0f / fmaxf(sqrtf(ss), L2_EPS);
        out[node * 3 + 0] = fmaf(p0, inv, brep[0]);
        out[node * 3 + 1] = fmaf(p1, inv, brep[1]);
        out[node * 3 + 2] = fmaf(p2, inv, brep[2]);
    }
}

// ------------------------- host -------------------------
extern "C" void kernel_launch(void* const* d_in, const int* in_sizes, int n_in,
                              void* d_out, int out_size) {
    const float* x    = (const float*)d_in[0];
    const void*  ei   = d_in[1];
    const float* W1   = (const float*)d_in[2];
    const float* b1   = (const float*)d_in[3];
    const float* W2   = (const float*)d_in[4];
    const float* b2   = (const float*)d_in[5];
    const float* W3   = (const float*)d_in[6];
    const float* b3   = (const float*)d_in[7];
    const float* W4   = (const float*)d_in[8];
    const float* b4   = (const float*)d_in[9];
    const float* g1   = (const float*)d_in[10];
    const float* be1  = (const float*)d_in[11];
    const float* g2   = (const float*)d_in[12];
    const float* be2  = (const float*)d_in[13];
    const float* g3   = (const float*)d_in[14];
    const float* be3  = (const float*)d_in[15];
    const float* Wrep = (const float*)d_in[16];
    const float* brep = (const float*)d_in[17];
    float* out = (float*)d_out;

    int E = in_sizes[1] / 2;
    if (E > EE) E = EE;

    static int s_attr_done = 0;
    if (!s_attr_done) {
        cudaFuncSetAttribute(k_gemm_f16, cudaFuncAttributeMaxDynamicSharedMemorySize, SMEM_GEMM);
        s_attr_done = 1;
    }

    const int TB = 256;
    int gN = (NN + TB - 1) / TB;
    int gE = (E + TB - 1) / TB;
    int gW8 = (NN + 7) / 8;
    int gSp = (NN + 8 * NPW - 1) / (8 * NPW);   // spmm128 blocks: 8 warps x NPW nodes
    int gScan = (NN + 1 + 511) / 512;
    int gBN = (NN * 64 + TB - 1) / TB;

    // ---- graph structure + weight prep (front-loaded) ----
    k_detect<<<1, 32>>>((const int*)ei);
    k_prepw<<<128, 256>>>(W2, 0);
    k_prepw<<<128, 256>>>(W3, 1);
    k_prepw<<<128, 256>>>(W4, 2);
    k_init<<<gN, TB>>>(x);
    k_count<<<gE, TB>>>(ei, E);
    k_dinv<<<gN, TB>>>();
    k_scan1<<<gScan, 512>>>();
    k_scan2<<<1, 1>>>(gScan);
    k_scan3<<<gScan, 512>>>();
    k_scatter<<<gE, TB>>>(ei, E);

    // ---- layer 1 (F=3) ----
    k_spmm3<<<gN, TB>>>(0, 1, -1);
    k_spmm3<<<gN, TB>>>(1, 2, 0);
    k_spmm3<<<gN, TB>>>(2, 3, 1);
    k_gemm1<<<(NN + 31) / 32, 256>>>(W1, b1);
    k_colstat1<<<NPB, 128>>>(0);
    k_colstat2<<<1, 128>>>(NPB, g1, be1);
    k_bnapply<<<gBN, TB>>>(0);

    // ---- layer 2 ----
    k_spmm128w<<<gSp, 256>>>(0, 1, -1);
    k_spmm128w<<<gSp, 256>>>(1, 2, 0);
    k_spmm128w<<<gSp, 256>>>(2, 3, 1);
    k_gemm_f16<<<NPB, 256, SMEM_GEMM>>>(b2, 0, 0);
    k_colstat2<<<1, 128>>>(NPB, g2, be2);
    k_bnapply<<<gBN, TB>>>(0);

    // ---- layer 3 ----
    k_spmm128w<<<gSp, 256>>>(0, 1, -1);
    k_spmm128w<<<gSp, 256>>>(1, 2, 0);
    k_spmm128w<<<gSp, 256>>>(2, 3, 1);
    k_gemm_f16<<<NPB, 256, SMEM_GEMM>>>(b3, 1, 1);
    k_colstat2<<<1, 128>>>(NPB, g3, be3);
    k_bnapply<<<gBN, TB>>>(1);

    // ---- layer 4 ----
    k_spmm128w<<<gSp, 256>>>(0, 1, -1);
    k_spmm128w<<<gSp, 256>>>(1, 2, 0);
    k_spmm128w<<<gSp, 256>>>(2, 3, 1);
    k_gemm_f16<<<NPB, 256, SMEM_GEMM>>>(b4, 2, -1);

    // ---- L2 norm + representation head ----
    k_final<<<gW8, 256>>>(Wrep, brep, out);
}

// round 14
// speedup vs baseline: 1.0850x; 1.0850x over previous
#include <cuda_runtime.h>
#include <cuda_bf16.h>
#include <cuda_fp16.h>
#include <math.h>
#include <stdint.h>

#define NN 100000
#define NN_PAD 100096
#define NPB (NN_PAD / 128)
#define EE 1600000
#define HID 128
#define NEG 0.01f
#define BN_EPS 1e-5f
#define L2_EPS 1e-12f

// ------------------------- device scratch -------------------------
__device__ uint32_t g_Thalf[(size_t)NN_PAD * 256]; // [T0|T1|T2|T3] fp16 packed, 64 half2/seg
__device__ float g_H[(size_t)NN * 128];            // GEMM output (pre-activation)
__device__ float g_t0[NN * 4];                     // layer-1 bases, float4-padded rows
__device__ float g_t1[NN * 4];
__device__ float g_t2[NN * 4];
__device__ float g_t3[NN * 4];
__device__ float g_dinv[NN];
__device__ int   g_indeg[NN];
__device__ int   g_ptr[NN + 1];
__device__ int   g_fill[NN];
__device__ int   g_bsums[256];
__device__ int2  g_edge[EE];
__device__ float g_part[NPB * 256];
__device__ float g_scale[128];
__device__ float g_shift[128];
__device__ uint32_t g_Wfhi[3 * 512 * 64];
__device__ uint32_t g_Wflo[3 * 512 * 64];
__device__ int   g_is64;

// ------------------------- helpers -------------------------
__device__ __forceinline__ uint32_t smem_u32(const void* p) {
    uint32_t a;
    asm("{ .reg .u64 t; cvta.to.shared.u64 t, %1; cvt.u32.u64 %0, t; }" : "=r"(a) : "l"(p));
    return a;
}

__device__ __forceinline__ uint32_t packh2(float a, float b) {
    __half2 h = __floats2half2_rn(a, b);
    return *reinterpret_cast<uint32_t*>(&h);
}

__device__ __forceinline__ void split2h(float x0, float x1, uint32_t& hi, uint32_t& lo) {
    __half h0 = __float2half_rn(x0);
    __half h1 = __float2half_rn(x1);
    float r0 = x0 - __half2float(h0);
    float r1 = x1 - __half2float(h1);
    __half2 H; H.x = h0; H.y = h1;
    hi = *reinterpret_cast<uint32_t*>(&H);
    lo = packh2(r0, r1);
}

#define MMAF16(c, a, b0, b1) \
    asm volatile("mma.sync.aligned.m16n8k16.row.col.f32.f16.f16.f32 " \
        "{%0,%1,%2,%3}, {%4,%5,%6,%7}, {%8,%9}, {%0,%1,%2,%3};" \
        : "+f"((c)[0]), "+f"((c)[1]), "+f"((c)[2]), "+f"((c)[3]) \
        : "r"((a)[0]), "r"((a)[1]), "r"((a)[2]), "r"((a)[3]), "r"(b0), "r"(b1))

#define LDSM4(r0, r1, r2, r3, a) \
    asm volatile("ldmatrix.sync.aligned.m8n8.x4.shared.b16 {%0,%1,%2,%3}, [%4];" \
        : "=r"(r0), "=r"(r1), "=r"(r2), "=r"(r3) : "r"(a))

#define LDSM4T(r0, r1, r2, r3, a) \
    asm volatile("ldmatrix.sync.aligned.m8n8.x4.trans.shared.b16 {%0,%1,%2,%3}, [%4];" \
        : "=r"(r0), "=r"(r1), "=r"(r2), "=r"(r3) : "r"(a))

__device__ __forceinline__ void cp16(uint32_t sdst, const void* gsrc) {
    asm volatile("cp.async.ca.shared.global [%0], [%1], 16;" :: "r"(sdst), "l"(gsrc) : "memory");
}

__device__ __forceinline__ void acc4(float* acc, uint2 v, float w) {
    float2 f0 = __half22float2(*reinterpret_cast<__half2*>(&v.x));
    float2 f1 = __half22float2(*reinterpret_cast<__half2*>(&v.y));
    acc[0] = fmaf(w, f0.x, acc[0]);
    acc[1] = fmaf(w, f0.y, acc[1]);
    acc[2] = fmaf(w, f1.x, acc[2]);
    acc[3] = fmaf(w, f1.y, acc[3]);
}

__device__ __forceinline__ float apply_act(float v, int act) {
    return act ? fmaxf(v, 0.0f) : (v >= 0.0f ? v : NEG * v);
}

// ------------------------- edge helpers -------------------------
__device__ __forceinline__ void load_edge(const void* ei, int E, int e, int& s, int& d) {
    if (g_is64) {
        const long long* p = (const long long*)ei;
        s = (int)p[e];
        d = (int)p[(size_t)E + e];
    } else {
        const int* p = (const int*)ei;
        s = p[e];
        d = p[E + e];
    }
}

// ------------------------- setup kernels -------------------------
__global__ void k_detect(const int* ei32) {
    if (threadIdx.x == 0 && blockIdx.x == 0) {
        int is64 = 1;
        for (int i = 0; i < 32; i++) {
            if (ei32[2 * i + 1] != 0) { is64 = 0; break; }
        }
        g_is64 = is64;
    }
}

// zero indeg + copy x into padded t0
__global__ void k_init(const float* __restrict__ x) {
    int i = blockIdx.x * blockDim.x + threadIdx.x;
    if (i < NN) {
        g_indeg[i] = 0;
        float4 v;
        v.x = x[3 * i];
        v.y = x[3 * i + 1];
        v.z = x[3 * i + 2];
        v.w = 0.0f;
        *(float4*)&g_t0[4 * i] = v;
    }
}

// symmetrized graph: in-degree == out-degree, count dst only
__global__ void k_count(const void* ei, int E) {
    int e = blockIdx.x * blockDim.x + threadIdx.x;
    if (e < E) {
        int s, d;
        load_edge(ei, E, e, s, d);
        atomicAdd(&g_indeg[d], 1);
    }
}

// scan over indeg; also computes dinv (folded former k_dinv)
__global__ void k_scan1() {
    __shared__ int sh[512];
    int gid = blockIdx.x * 512 + threadIdx.x;
    int v = (gid < NN) ? g_indeg[gid] : 0;
    if (gid < NN) {
        float dg = (float)v;
        g_dinv[gid] = (dg > 0.0f) ? rsqrtf(fmaxf(dg, 1.0f)) : 0.0f;
    }
    sh[threadIdx.x] = v;
    __syncthreads();
    for (int off = 1; off < 512; off <<= 1) {
        int t = (threadIdx.x >= off) ? sh[threadIdx.x - off] : 0;
        __syncthreads();
        sh[threadIdx.x] += t;
        __syncthreads();
    }
    if (gid <= NN) g_ptr[gid] = sh[threadIdx.x] - v;
    if (threadIdx.x == 511) g_bsums[blockIdx.x] = sh[511];
}

__global__ void k_scan2(int nb) {
    if (threadIdx.x == 0 && blockIdx.x == 0) {
        int acc = 0;
        for (int i = 0; i < nb; i++) { int t = g_bsums[i]; g_bsums[i] = acc; acc += t; }
    }
}

__global__ void k_scan3() {
    int gid = blockIdx.x * 512 + threadIdx.x;
    if (gid <= NN) {
        int p = g_ptr[gid] + g_bsums[blockIdx.x];
        g_ptr[gid] = p;
        if (gid < NN) g_fill[gid] = p;
    }
}

__global__ void k_scatter(const void* ei, int E) {
    int e = blockIdx.x * blockDim.x + threadIdx.x;
    if (e < E) {
        int s, d;
        load_edge(ei, E, e, s, d);
        float w = -(g_dinv[s] * g_dinv[d]);
        int pos = atomicAdd(&g_fill[d], 1);
        g_edge[pos] = make_int2(s, __float_as_int(w));
    }
}

// ------------------------- layer-1 sparse (F=3, float4 rows) -------------------------
__global__ void k_spmm3(int xc, int yc, int subc) {
    int i = blockIdx.x * blockDim.x + threadIdx.x;
    if (i >= NN) return;
    const float4* X = (const float4*)((xc == 0) ? g_t0 : (xc == 1) ? g_t1 : (xc == 2) ? g_t2 : g_t3);
    float4*       Y = (float4*)((yc == 1) ? g_t1 : (yc == 2) ? g_t2 : g_t3);
    int b = g_ptr[i], en = g_ptr[i + 1];
    float a0 = 0, a1 = 0, a2 = 0;
    int e = b;
    for (; e + 4 <= en; e += 4) {
        int2 e0 = __ldg(&g_edge[e]);
        int2 e1 = __ldg(&g_edge[e + 1]);
        int2 e2 = __ldg(&g_edge[e + 2]);
        int2 e3 = __ldg(&g_edge[e + 3]);
        float4 v0 = __ldg(&X[e0.x]);
        float4 v1 = __ldg(&X[e1.x]);
        float4 v2 = __ldg(&X[e2.x]);
        float4 v3 = __ldg(&X[e3.x]);
        float w0 = __int_as_float(e0.y), w1 = __int_as_float(e1.y);
        float w2 = __int_as_float(e2.y), w3 = __int_as_float(e3.y);
        a0 = fmaf(w0, v0.x, a0); a1 = fmaf(w0, v0.y, a1); a2 = fmaf(w0, v0.z, a2);
        a0 = fmaf(w1, v1.x, a0); a1 = fmaf(w1, v1.y, a1); a2 = fmaf(w1, v1.z, a2);
        a0 = fmaf(w2, v2.x, a0); a1 = fmaf(w2, v2.y, a1); a2 = fmaf(w2, v2.z, a2);
        a0 = fmaf(w3, v3.x, a0); a1 = fmaf(w3, v3.y, a1); a2 = fmaf(w3, v3.z, a2);
    }
    for (; e < en; e++) {
        int2 ed = __ldg(&g_edge[e]);
        float ww = __int_as_float(ed.y);
        float4 v = __ldg(&X[ed.x]);
        a0 = fmaf(ww, v.x, a0);
        a1 = fmaf(ww, v.y, a1);
        a2 = fmaf(ww, v.z, a2);
    }
    float4 o;
    if (subc < 0) {
        o = make_float4(a0, a1, a2, 0.0f);
    } else {
        const float4* S = (const float4*)((subc == 0) ? g_t0 : (subc == 1) ? g_t1 : (subc == 2) ? g_t2 : g_t3);
        float4 s = S[i];
        o = make_float4(2.0f * a0 - s.x, 2.0f * a1 - s.y, 2.0f * a2 - s.z, 0.0f);
    }
    Y[i] = o;
}

// ------------------------- F=128 SpMM: warp per node, fp16 in/out (R12 form) ---------------
__global__ void __launch_bounds__(256) k_spmm128w(int xseg, int yseg, int subseg) {
    int node = blockIdx.x * 8 + (threadIdx.x >> 5);
    if (node >= NN) return;
    int lane = threadIdx.x & 31;
    int b = g_ptr[node], en = g_ptr[node + 1];
    float acc[4] = {0, 0, 0, 0};
    const uint2* Xb = (const uint2*)g_Thalf;       // row = 128 uint2
    const uint32_t xo = xseg * 32 + lane;

    int e = b;
    for (; e + 4 <= en; e += 4) {
        int2 e0 = __ldg(&g_edge[e]);
        int2 e1 = __ldg(&g_edge[e + 1]);
        int2 e2 = __ldg(&g_edge[e + 2]);
        int2 e3 = __ldg(&g_edge[e + 3]);
        uint2 v0 = __ldg(&Xb[(size_t)e0.x * 128 + xo]);
        uint2 v1 = __ldg(&Xb[(size_t)e1.x * 128 + xo]);
        uint2 v2 = __ldg(&Xb[(size_t)e2.x * 128 + xo]);
        uint2 v3 = __ldg(&Xb[(size_t)e3.x * 128 + xo]);
        acc4(acc, v0, __int_as_float(e0.y));
        acc4(acc, v1, __int_as_float(e1.y));
        acc4(acc, v2, __int_as_float(e2.y));
        acc4(acc, v3, __int_as_float(e3.y));
    }
    for (; e < en; e++) {
        int2 ed = __ldg(&g_edge[e]);
        uint2 v = __ldg(&Xb[(size_t)ed.x * 128 + xo]);
        acc4(acc, v, __int_as_float(ed.y));
    }

    if (subseg >= 0) {
        uint2 s = __ldg((const uint2*)g_Thalf + (size_t)node * 128 + subseg * 32 + lane);
        float2 s0 = __half22float2(*reinterpret_cast<__half2*>(&s.x));
        float2 s1 = __half22float2(*reinterpret_cast<__half2*>(&s.y));
        acc[0] = 2.0f * acc[0] - s0.x;
        acc[1] = 2.0f * acc[1] - s0.y;
        acc[2] = 2.0f * acc[2] - s1.x;
        acc[3] = 2.0f * acc[3] - s1.y;
    }
    uint2 o;
    o.x = packh2(acc[0], acc[1]);
    o.y = packh2(acc[2], acc[3]);
    *((uint2*)g_Thalf + (size_t)node * 128 + yseg * 32 + lane) = o;
}

// ------------------------- layer-1 GEMM (12 x 128) -------------------------
__global__ void __launch_bounds__(256) k_gemm1(const float* __restrict__ W1,
                                               const float* __restrict__ b1) {
    __shared__ float shW[12 * 128];
    __shared__ float shT[32 * 12];
    int tid = threadIdx.x;
    for (int i = tid; i < 1536; i += 256) shW[i] = W1[i];
    int r0 = blockIdx.x * 32;
    for (int i = tid; i < 384; i += 256) {
        int r = i / 12, j = i % 12;
        int k = j / 3, d = j % 3;
        int gr = r0 + r;
        float v = 0.0f;
        if (gr < NN) {
            const float* src = (k == 0) ? g_t0 : (k == 1) ? g_t1 : (k == 2) ? g_t2 : g_t3;
            v = src[gr * 4 + d];
        }
        shT[i] = v;
    }
    __syncthreads();
    int r = tid >> 3;
    int c0 = (tid & 7) * 16;
    int gr = r0 + r;
    if (gr < NN) {
        #pragma unroll
        for (int c = c0; c < c0 + 16; c++) {
            float acc = b1[c];
            #pragma unroll
            for (int j = 0; j < 12; j++) acc = fmaf(shT[r * 12 + j], shW[j * 128 + c], acc);
            g_H[(size_t)gr * 128 + c] = acc;
        }
    }
}

// ------------------------- weight prep -------------------------
__global__ void k_prepw(const float* __restrict__ W, int widx) {
    int i = blockIdx.x * 256 + threadIdx.x;
    if (i < 512 * 64) {
        int k = i >> 6, np = i & 63;
        float x0 = W[k * 128 + 2 * np];
        float x1 = W[k * 128 + 2 * np + 1];
        uint32_t hi, lo;
        split2h(x0, x1, hi, lo);
        g_Wfhi[widx * 512 * 64 + i] = hi;
        g_Wflo[widx * 512 * 64 + i] = lo;
    }
}

// ------------------------- fp16 2-term ldmatrix GEMM, 3-stage pipeline, fused BN stats ----
#define AST 20
#define BSTU 68
#define A_UINTS (128 * AST)
#define B_UINTS (32 * BSTU)
#define STAGE_UINTS (A_UINTS + 2 * B_UINTS)
#define SMEM_GEMM (3 * STAGE_UINTS * 4)

__global__ void __launch_bounds__(256, 2) k_gemm_f16(const float* __restrict__ bias,
                                                     int widx, int act) {
    extern __shared__ uint32_t sm[];
    const int tid = threadIdx.x;
    const int lane = tid & 31;
    const int wid = tid >> 5;
    const int wm = wid & 3;
    const int wn = wid >> 2;
    const int lk = lane & 3;
    const int lr = lane >> 2;
    const int row0 = blockIdx.x * 128;
    const uint32_t sbase = smem_u32(sm);
    const uint32_t* Whi = g_Wfhi + widx * 512 * 64;
    const uint32_t* Wlo = g_Wflo + widx * 512 * 64;

    float acc[2][8][4];
    #pragma unroll
    for (int mt = 0; mt < 2; mt++)
        #pragma unroll
        for (int nt = 0; nt < 8; nt++)
            #pragma unroll
            for (int q = 0; q < 4; q++) acc[mt][nt][q] = 0.0f;

    const int laneRow = lane & 15;
    const int laneHi = lane >> 4;
    const uint32_t aLaneOff = (uint32_t)((wm * 32 + laneRow) * 80 + laneHi * 16);
    const uint32_t bLaneOff = (uint32_t)(laneRow * 272 + (wn * 64 + laneHi * 8) * 2);

    auto issue = [&](int c, int stage) {
        uint32_t Ab  = sbase + stage * STAGE_UINTS * 4;
        uint32_t Bhb = Ab + A_UINTS * 4;
        uint32_t Blb = Bhb + B_UINTS * 4;
        int auoff = (c >> 2) * 64 + (c & 3) * 16;
        #pragma unroll
        for (int j = 0; j < 2; j++) {
            int q = tid * 2 + j;
            int r = q >> 2, s4 = (q & 3) * 4;
            cp16(Ab + (r * AST + s4) * 4,
                 g_Thalf + (size_t)(row0 + r) * 256 + auoff + s4);
        }
        int kb = c * 32;
        #pragma unroll
        for (int j = 0; j < 2; j++) {
            int q = tid * 2 + j;
            int kr = q >> 4, n4 = (q & 15) * 4;
            cp16(Bhb + (kr * BSTU + n4) * 4, Whi + (kb + kr) * 64 + n4);
            cp16(Blb + (kr * BSTU + n4) * 4, Wlo + (kb + kr) * 64 + n4);
        }
        asm volatile("cp.async.commit_group;" ::: "memory");
    };

    issue(0, 0);
    issue(1, 1);

    for (int c = 0; c < 16; c++) {
        asm volatile("cp.async.wait_group 1;" ::: "memory");
        __syncthreads();
        if (c + 2 < 16)
            issue(c + 2, (c + 2) % 3);
        {
            uint32_t Ab = sbase + (c % 3) * STAGE_UINTS * 4;
            uint32_t Bb = Ab + A_UINTS * 4;
            #pragma unroll
            for (int ks = 0; ks < 2; ks++) {
                uint32_t a[2][4];
                #pragma unroll
                for (int mt = 0; mt < 2; mt++) {
                    uint32_t addr = Ab + aLaneOff + (uint32_t)(mt * 16 * 80 + ks * 32);
                    LDSM4(a[mt][0], a[mt][1], a[mt][2], a[mt][3], addr);
                }
                #pragma unroll
                for (int ntp = 0; ntp < 4; ntp++) {
                    uint32_t baddr = Bb + bLaneOff + (uint32_t)(ks * 16 * 272 + ntp * 32);
                    uint32_t h0, h1, h2, h3;
                    LDSM4T(h0, h1, h2, h3, baddr);
                    MMAF16(acc[0][2 * ntp],     a[0], h0, h1);
                    MMAF16(acc[1][2 * ntp],     a[1], h0, h1);
                    MMAF16(acc[0][2 * ntp + 1], a[0], h2, h3);
                    MMAF16(acc[1][2 * ntp + 1], a[1], h2, h3);
                    uint32_t l0, l1, l2, l3;
                    LDSM4T(l0, l1, l2, l3, baddr + B_UINTS * 4);
                    MMAF16(acc[0][2 * ntp],     a[0], l0, l1);
                    MMAF16(acc[1][2 * ntp],     a[1], l0, l1);
                    MMAF16(acc[0][2 * ntp + 1], a[0], l2, l3);
                    MMAF16(acc[1][2 * ntp + 1], a[1], l2, l3);
                }
            }
        }
        __syncthreads();
    }

    const int r1b = row0 + wm * 32 + lr;
    #pragma unroll
    for (int mt = 0; mt < 2; mt++) {
        int r1 = r1b + mt * 16;
        int r2 = r1 + 8;
        #pragma unroll
        for (int nt = 0; nt < 8; nt++) {
            int col = wn * 64 + nt * 8 + 2 * lk;
            float2 bs = *(const float2*)&bias[col];
            acc[mt][nt][0] += bs.x; acc[mt][nt][1] += bs.y;
            acc[mt][nt][2] += bs.x; acc[mt][nt][3] += bs.y;
            if (r1 < NN)
                *(float2*)&g_H[(size_t)r1 * 128 + col] = make_float2(acc[mt][nt][0], acc[mt][nt][1]);
            if (r2 < NN)
                *(float2*)&g_H[(size_t)r2 * 128 + col] = make_float2(acc[mt][nt][2], acc[mt][nt][3]);
        }
    }

    if (act >= 0) {
        float* sred = (float*)sm;
        __syncthreads();
        #pragma unroll
        for (int nt = 0; nt < 8; nt++) {
            float s0 = 0, s1 = 0, q0 = 0, q1 = 0;
            #pragma unroll
            for (int mt = 0; mt < 2; mt++) {
                int r1 = r1b + mt * 16;
                int r2 = r1 + 8;
                if (r1 < NN) {
                    float v0 = apply_act(acc[mt][nt][0], act);
                    float v1 = apply_act(acc[mt][nt][1], act);
                    s0 += v0; q0 = fmaf(v0, v0, q0);
                    s1 += v1; q1 = fmaf(v1, v1, q1);
                }
                if (r2 < NN) {
                    float v0 = apply_act(acc[mt][nt][2], act);
                    float v1 = apply_act(acc[mt][nt][3], act);
                    s0 += v0; q0 = fmaf(v0, v0, q0);
                    s1 += v1; q1 = fmaf(v1, v1, q1);
                }
            }
            #pragma unroll
            for (int o = 4; o < 32; o <<= 1) {
                s0 += __shfl_xor_sync(0xFFFFFFFFu, s0, o);
                s1 += __shfl_xor_sync(0xFFFFFFFFu, s1, o);
                q0 += __shfl_xor_sync(0xFFFFFFFFu, q0, o);
                q1 += __shfl_xor_sync(0xFFFFFFFFu, q1, o);
            }
            if (lr == 0) {
                int col = wn * 64 + nt * 8 + 2 * lk;
                sred[wm * 256 + col] = s0;
                sred[wm * 256 + col + 1] = s1;
                sred[wm * 256 + 128 + col] = q0;
                sred[wm * 256 + 128 + col + 1] = q1;
            }
        }
        __syncthreads();
        g_part[blockIdx.x * 256 + tid] =
            sred[tid] + sred[256 + tid] + sred[512 + tid] + sred[768 + tid];
    }
}

// ------------------------- layer-1 column stats (strided) -------------------------
__global__ void __launch_bounds__(128) k_colstat1(int act) {
    int c = threadIdx.x;
    float s = 0.0f, s2 = 0.0f;
    for (int r = blockIdx.x; r < NN; r += NPB) {
        float v = g_H[(size_t)r * 128 + c];
        v = apply_act(v, act);
        s += v;
        s2 = fmaf(v, v, s2);
    }
    g_part[blockIdx.x * 256 + c] = s;
    g_part[blockIdx.x * 256 + 128 + c] = s2;
}

// ------------------------- BN scale/shift from partials -------------------------
__global__ void __launch_bounds__(128) k_colstat2(int nb,
                                                  const float* __restrict__ gamma,
                                                  const float* __restrict__ beta) {
    int c = threadIdx.x;
    float s = 0.0f, s2 = 0.0f;
    for (int b = 0; b < nb; b++) {
        s += g_part[b * 256 + c];
        s2 += g_part[b * 256 + 128 + c];
    }
    float mu = s / (float)NN;
    float var = s2 / (float)NN - mu * mu;
    float sc = gamma[c] * rsqrtf(var + BN_EPS);
    g_scale[c] = sc;
    g_shift[c] = beta[c] - mu * sc;
}

// float4 reads, uint4 writes: one thread per 4 half2
__global__ void __launch_bounds__(256) k_bnapply(int act) {
    int idx = blockIdx.x * blockDim.x + threadIdx.x;
    if (idx < NN * 32) {
        int p = idx & 31;          // group of 4 columns-pairs
        int r = idx >> 5;
        int c = p * 4;
        float4 h0 = *(const float4*)&g_H[(size_t)r * 128 + c];
        float v0 = fmaf(apply_act(h0.x, act), g_scale[c],     g_shift[c]);
        float v1 = fmaf(apply_act(h0.y, act), g_scale[c + 1], g_shift[c + 1]);
        float v2 = fmaf(apply_act(h0.z, act), g_scale[c + 2], g_shift[c + 2]);
        float v3 = fmaf(apply_act(h0.w, act), g_scale[c + 3], g_shift[c + 3]);
        uint2 o;
        o.x = packh2(v0, v1);
        o.y = packh2(v2, v3);
        *((uint2*)g_Thalf + (size_t)r * 128 + p) = o;
    }
}

// ------------------------- final: L2 norm + head -------------------------
__global__ void __launch_bounds__(256) k_final(const float* __restrict__ Wrep,
                                               const float* __restrict__ brep,
                                               float* __restrict__ out) {
    __shared__ float shW[384];
    int tid = threadIdx.x;
    for (int i = tid; i < 384; i += 256) shW[i] = Wrep[i];
    __syncthreads();
    int node = blockIdx.x * 8 + (tid >> 5);
    int lane = tid & 31;
    if (node >= NN) return;
    float4 h = *(const float4*)&g_H[(size_t)node * 128 + lane * 4];
    float hv[4] = {h.x, h.y, h.z, h.w};
    float ss = 0.0f, p0 = 0.0f, p1 = 0.0f, p2 = 0.0f;
    #pragma unroll
    for (int q = 0; q < 4; q++) {
        int f = lane * 4 + q;
        ss = fmaf(hv[q], hv[q], ss);
        p0 = fmaf(hv[q], shW[f * 3 + 0], p0);
        p1 = fmaf(hv[q], shW[f * 3 + 1], p1);
        p2 = fmaf(hv[q], shW[f * 3 + 2], p2);
    }
    #pragma unroll
    for (int o = 16; o > 0; o >>= 1) {
        ss += __shfl_xor_sync(0xFFFFFFFFu, ss, o);
        p0 += __shfl_xor_sync(0xFFFFFFFFu, p0, o);
        p1 += __shfl_xor_sync(0xFFFFFFFFu, p1, o);
        p2 += __shfl_xor_sync(0xFFFFFFFFu, p2, o);
    }
    if (lane == 0) {
        float inv = 1.0f / fmaxf(sqrtf(ss), L2_EPS);
        out[node * 3 + 0] = fmaf(p0, inv, brep[0]);
        out[node * 3 + 1] = fmaf(p1, inv, brep[1]);
        out[node * 3 + 2] = fmaf(p2, inv, brep[2]);
    }
}

// ------------------------- host -------------------------
extern "C" void kernel_launch(void* const* d_in, const int* in_sizes, int n_in,
                              void* d_out, int out_size) {
    const float* x    = (const float*)d_in[0];
    const void*  ei   = d_in[1];
    const float* W1   = (const float*)d_in[2];
    const float* b1   = (const float*)d_in[3];
    const float* W2   = (const float*)d_in[4];
    const float* b2   = (const float*)d_in[5];
    const float* W3   = (const float*)d_in[6];
    const float* b3   = (const float*)d_in[7];
    const float* W4   = (const float*)d_in[8];
    const float* b4   = (const float*)d_in[9];
    const float* g1   = (const float*)d_in[10];
    const float* be1  = (const float*)d_in[11];
    const float* g2   = (const float*)d_in[12];
    const float* be2  = (const float*)d_in[13];
    const float* g3   = (const float*)d_in[14];
    const float* be3  = (const float*)d_in[15];
    const float* Wrep = (const float*)d_in[16];
    const float* brep = (const float*)d_in[17];
    float* out = (float*)d_out;

    int E = in_sizes[1] / 2;
    if (E > EE) E = EE;

    static int s_attr_done = 0;
    if (!s_attr_done) {
        cudaFuncSetAttribute(k_gemm_f16, cudaFuncAttributeMaxDynamicSharedMemorySize, SMEM_GEMM);
        s_attr_done = 1;
    }

    const int TB = 256;
    int gN = (NN + TB - 1) / TB;
    int gE = (E + TB - 1) / TB;
    int gW8 = (NN + 7) / 8;
    int gScan = (NN + 1 + 511) / 512;
    int gBN = (NN * 32 + TB - 1) / TB;

    // ---- graph structure + weight prep (front-loaded) ----
    k_detect<<<1, 32>>>((const int*)ei);
    k_prepw<<<128, 256>>>(W2, 0);
    k_prepw<<<128, 256>>>(W3, 1);
    k_prepw<<<128, 256>>>(W4, 2);
    k_init<<<gN, TB>>>(x);
    k_count<<<gE, TB>>>(ei, E);
    k_scan1<<<gScan, 512>>>();
    k_scan2<<<1, 1>>>(gScan);
    k_scan3<<<gScan, 512>>>();
    k_scatter<<<gE, TB>>>(ei, E);

    // ---- layer 1 (F=3) ----
    k_spmm3<<<gN, TB>>>(0, 1, -1);
    k_spmm3<<<gN, TB>>>(1, 2, 0);
    k_spmm3<<<gN, TB>>>(2, 3, 1);
    k_gemm1<<<(NN + 31) / 32, 256>>>(W1, b1);
    k_colstat1<<<NPB, 128>>>(0);
    k_colstat2<<<1, 128>>>(NPB, g1, be1);
    k_bnapply<<<gBN, TB>>>(0);

    // ---- layer 2 ----
    k_spmm128w<<<gW8, 256>>>(0, 1, -1);
    k_spmm128w<<<gW8, 256>>>(1, 2, 0);
    k_spmm128w<<<gW8, 256>>>(2, 3, 1);
    k_gemm_f16<<<NPB, 256, SMEM_GEMM>>>(b2, 0, 0);
    k_colstat2<<<1, 128>>>(NPB, g2, be2);
    k_bnapply<<<gBN, TB>>>(0);

    // ---- layer 3 ----
    k_spmm128w<<<gW8, 256>>>(0, 1, -1);
    k_spmm128w<<<gW8, 256>>>(1, 2, 0);
    k_spmm128w<<<gW8, 256>>>(2, 3, 1);
    k_gemm_f16<<<NPB, 256, SMEM_GEMM>>>(b3, 1, 1);
    k_colstat2<<<1, 128>>>(NPB, g3, be3);
    k_bnapply<<<gBN, TB>>>(1);

    // ---- layer 4 ----
    k_spmm128w<<<gW8, 256>>>(0, 1, -1);
    k_spmm128w<<<gW8, 256>>>(1, 2, 0);
    k_spmm128w<<<gW8, 256>>>(2, 3, 1);
    k_gemm_f16<<<NPB, 256, SMEM_GEMM>>>(b4, 2, -1);

    // ---- L2 norm + representation head ----
    k_final<<<gW8, 256>>>(Wrep, brep, out);
}

// round 15
// speedup vs baseline: 1.2083x; 1.1136x over previous
#include <cuda_runtime.h>
#include <cuda_bf16.h>
#include <cuda_fp16.h>
#include <math.h>
#include <stdint.h>

#define NN 100000
#define NN_PAD 100096
#define NPB (NN_PAD / 128)
#define EE 1600000
#define HID 128
#define NEG 0.01f
#define BN_EPS 1e-5f
#define L2_EPS 1e-12f

// ------------------------- device scratch -------------------------
__device__ uint32_t g_Thalf[(size_t)NN_PAD * 256]; // [T0|T1|T2|T3] fp16 packed, 64 half2/seg
__device__ float g_H[(size_t)NN * 128];            // GEMM output (pre-activation)
__device__ float g_t0[NN * 4];                     // layer-1 bases, float4-padded rows
__device__ float g_t1[NN * 4];
__device__ float g_t2[NN * 4];
__device__ float g_t3[NN * 4];
__device__ float g_dinv[NN];
__device__ int   g_indeg[NN];
__device__ int   g_ptr[NN + 1];
__device__ int   g_fill[NN];
__device__ int   g_bsums[256];
__device__ int2  g_edge[EE];
__device__ float g_part[NPB * 256];
__device__ float g_scale[128];
__device__ float g_shift[128];
__device__ uint32_t g_Wfhi[3 * 512 * 64];
__device__ uint32_t g_Wflo[3 * 512 * 64];
__device__ int   g_is64;

// ------------------------- helpers -------------------------
__device__ __forceinline__ uint32_t smem_u32(const void* p) {
    uint32_t a;
    asm("{ .reg .u64 t; cvta.to.shared.u64 t, %1; cvt.u32.u64 %0, t; }" : "=r"(a) : "l"(p));
    return a;
}

__device__ __forceinline__ uint32_t packh2(float a, float b) {
    __half2 h = __floats2half2_rn(a, b);
    return *reinterpret_cast<uint32_t*>(&h);
}

__device__ __forceinline__ void split2h(float x0, float x1, uint32_t& hi, uint32_t& lo) {
    __half h0 = __float2half_rn(x0);
    __half h1 = __float2half_rn(x1);
    float r0 = x0 - __half2float(h0);
    float r1 = x1 - __half2float(h1);
    __half2 H; H.x = h0; H.y = h1;
    hi = *reinterpret_cast<uint32_t*>(&H);
    lo = packh2(r0, r1);
}

#define MMAF16(c, a, b0, b1) \
    asm volatile("mma.sync.aligned.m16n8k16.row.col.f32.f16.f16.f32 " \
        "{%0,%1,%2,%3}, {%4,%5,%6,%7}, {%8,%9}, {%0,%1,%2,%3};" \
        : "+f"((c)[0]), "+f"((c)[1]), "+f"((c)[2]), "+f"((c)[3]) \
        : "r"((a)[0]), "r"((a)[1]), "r"((a)[2]), "r"((a)[3]), "r"(b0), "r"(b1))

#define LDSM4(r0, r1, r2, r3, a) \
    asm volatile("ldmatrix.sync.aligned.m8n8.x4.shared.b16 {%0,%1,%2,%3}, [%4];" \
        : "=r"(r0), "=r"(r1), "=r"(r2), "=r"(r3) : "r"(a))

#define LDSM4T(r0, r1, r2, r3, a) \
    asm volatile("ldmatrix.sync.aligned.m8n8.x4.trans.shared.b16 {%0,%1,%2,%3}, [%4];" \
        : "=r"(r0), "=r"(r1), "=r"(r2), "=r"(r3) : "r"(a))

__device__ __forceinline__ void cp16(uint32_t sdst, const void* gsrc) {
    asm volatile("cp.async.ca.shared.global [%0], [%1], 16;" :: "r"(sdst), "l"(gsrc) : "memory");
}

__device__ __forceinline__ void acc4(float* acc, uint2 v, float w) {
    float2 f0 = __half22float2(*reinterpret_cast<__half2*>(&v.x));
    float2 f1 = __half22float2(*reinterpret_cast<__half2*>(&v.y));
    acc[0] = fmaf(w, f0.x, acc[0]);
    acc[1] = fmaf(w, f0.y, acc[1]);
    acc[2] = fmaf(w, f1.x, acc[2]);
    acc[3] = fmaf(w, f1.y, acc[3]);
}

__device__ __forceinline__ float apply_act(float v, int act) {
    return act ? fmaxf(v, 0.0f) : (v >= 0.0f ? v : NEG * v);
}

// ------------------------- edge helpers -------------------------
__device__ __forceinline__ void load_edge(const void* ei, int E, int e, int& s, int& d) {
    if (g_is64) {
        const long long* p = (const long long*)ei;
        s = (int)p[e];
        d = (int)p[(size_t)E + e];
    } else {
        const int* p = (const int*)ei;
        s = p[e];
        d = p[E + e];
    }
}

// ------------------------- setup kernels -------------------------
__global__ void k_detect(const int* ei32) {
    if (threadIdx.x == 0 && blockIdx.x == 0) {
        int is64 = 1;
        for (int i = 0; i < 32; i++) {
            if (ei32[2 * i + 1] != 0) { is64 = 0; break; }
        }
        g_is64 = is64;
    }
}

__global__ void k_init(const float* __restrict__ x) {
    int i = blockIdx.x * blockDim.x + threadIdx.x;
    if (i < NN) {
        g_indeg[i] = 0;
        float4 v;
        v.x = x[3 * i];
        v.y = x[3 * i + 1];
        v.z = x[3 * i + 2];
        v.w = 0.0f;
        *(float4*)&g_t0[4 * i] = v;
    }
}

__global__ void k_count(const void* ei, int E) {
    int e = blockIdx.x * blockDim.x + threadIdx.x;
    if (e < E) {
        int s, d;
        load_edge(ei, E, e, s, d);
        atomicAdd(&g_indeg[d], 1);
    }
}

// scan over indeg; also computes dinv
__global__ void k_scan1() {
    __shared__ int sh[512];
    int gid = blockIdx.x * 512 + threadIdx.x;
    int v = (gid < NN) ? g_indeg[gid] : 0;
    if (gid < NN) {
        float dg = (float)v;
        g_dinv[gid] = (dg > 0.0f) ? rsqrtf(fmaxf(dg, 1.0f)) : 0.0f;
    }
    sh[threadIdx.x] = v;
    __syncthreads();
    for (int off = 1; off < 512; off <<= 1) {
        int t = (threadIdx.x >= off) ? sh[threadIdx.x - off] : 0;
        __syncthreads();
        sh[threadIdx.x] += t;
        __syncthreads();
    }
    if (gid <= NN) g_ptr[gid] = sh[threadIdx.x] - v;
    if (threadIdx.x == 511) g_bsums[blockIdx.x] = sh[511];
}

__global__ void k_scan2(int nb) {
    if (threadIdx.x == 0 && blockIdx.x == 0) {
        int acc = 0;
        for (int i = 0; i < nb; i++) { int t = g_bsums[i]; g_bsums[i] = acc; acc += t; }
    }
}

__global__ void k_scan3() {
    int gid = blockIdx.x * 512 + threadIdx.x;
    if (gid <= NN) {
        int p = g_ptr[gid] + g_bsums[blockIdx.x];
        g_ptr[gid] = p;
        if (gid < NN) g_fill[gid] = p;
    }
}

__global__ void k_scatter(const void* ei, int E) {
    int e = blockIdx.x * blockDim.x + threadIdx.x;
    if (e < E) {
        int s, d;
        load_edge(ei, E, e, s, d);
        float w = -(g_dinv[s] * g_dinv[d]);
        int pos = atomicAdd(&g_fill[d], 1);
        g_edge[pos] = make_int2(s, __float_as_int(w));
    }
}

// ------------------------- layer-1 sparse (F=3, float4 rows) -------------------------
__global__ void k_spmm3(int xc, int yc, int subc) {
    int i = blockIdx.x * blockDim.x + threadIdx.x;
    if (i >= NN) return;
    const float4* X = (const float4*)((xc == 0) ? g_t0 : (xc == 1) ? g_t1 : (xc == 2) ? g_t2 : g_t3);
    float4*       Y = (float4*)((yc == 1) ? g_t1 : (yc == 2) ? g_t2 : g_t3);
    int b = g_ptr[i], en = g_ptr[i + 1];
    float a0 = 0, a1 = 0, a2 = 0;
    int e = b;
    for (; e + 4 <= en; e += 4) {
        int2 e0 = __ldg(&g_edge[e]);
        int2 e1 = __ldg(&g_edge[e + 1]);
        int2 e2 = __ldg(&g_edge[e + 2]);
        int2 e3 = __ldg(&g_edge[e + 3]);
        float4 v0 = __ldg(&X[e0.x]);
        float4 v1 = __ldg(&X[e1.x]);
        float4 v2 = __ldg(&X[e2.x]);
        float4 v3 = __ldg(&X[e3.x]);
        float w0 = __int_as_float(e0.y), w1 = __int_as_float(e1.y);
        float w2 = __int_as_float(e2.y), w3 = __int_as_float(e3.y);
        a0 = fmaf(w0, v0.x, a0); a1 = fmaf(w0, v0.y, a1); a2 = fmaf(w0, v0.z, a2);
        a0 = fmaf(w1, v1.x, a0); a1 = fmaf(w1, v1.y, a1); a2 = fmaf(w1, v1.z, a2);
        a0 = fmaf(w2, v2.x, a0); a1 = fmaf(w2, v2.y, a1); a2 = fmaf(w2, v2.z, a2);
        a0 = fmaf(w3, v3.x, a0); a1 = fmaf(w3, v3.y, a1); a2 = fmaf(w3, v3.z, a2);
    }
    for (; e < en; e++) {
        int2 ed = __ldg(&g_edge[e]);
        float ww = __int_as_float(ed.y);
        float4 v = __ldg(&X[ed.x]);
        a0 = fmaf(ww, v.x, a0);
        a1 = fmaf(ww, v.y, a1);
        a2 = fmaf(ww, v.z, a2);
    }
    float4 o;
    if (subc < 0) {
        o = make_float4(a0, a1, a2, 0.0f);
    } else {
        const float4* S = (const float4*)((subc == 0) ? g_t0 : (subc == 1) ? g_t1 : (subc == 2) ? g_t2 : g_t3);
        float4 s = S[i];
        o = make_float4(2.0f * a0 - s.x, 2.0f * a1 - s.y, 2.0f * a2 - s.z, 0.0f);
    }
    Y[i] = o;
}

// ------------------------- F=128 SpMM: warp per node, fp16 in/out (frozen R12 form) --------
__global__ void __launch_bounds__(256) k_spmm128w(int xseg, int yseg, int subseg) {
    int node = blockIdx.x * 8 + (threadIdx.x >> 5);
    if (node >= NN) return;
    int lane = threadIdx.x & 31;
    int b = g_ptr[node], en = g_ptr[node + 1];
    float acc[4] = {0, 0, 0, 0};
    const uint2* Xb = (const uint2*)g_Thalf;       // row = 128 uint2
    const uint32_t xo = xseg * 32 + lane;

    int e = b;
    for (; e + 4 <= en; e += 4) {
        int2 e0 = __ldg(&g_edge[e]);
        int2 e1 = __ldg(&g_edge[e + 1]);
        int2 e2 = __ldg(&g_edge[e + 2]);
        int2 e3 = __ldg(&g_edge[e + 3]);
        uint2 v0 = __ldg(&Xb[(size_t)e0.x * 128 + xo]);
        uint2 v1 = __ldg(&Xb[(size_t)e1.x * 128 + xo]);
        uint2 v2 = __ldg(&Xb[(size_t)e2.x * 128 + xo]);
        uint2 v3 = __ldg(&Xb[(size_t)e3.x * 128 + xo]);
        acc4(acc, v0, __int_as_float(e0.y));
        acc4(acc, v1, __int_as_float(e1.y));
        acc4(acc, v2, __int_as_float(e2.y));
        acc4(acc, v3, __int_as_float(e3.y));
    }
    for (; e < en; e++) {
        int2 ed = __ldg(&g_edge[e]);
        uint2 v = __ldg(&Xb[(size_t)ed.x * 128 + xo]);
        acc4(acc, v, __int_as_float(ed.y));
    }

    if (subseg >= 0) {
        uint2 s = __ldg((const uint2*)g_Thalf + (size_t)node * 128 + subseg * 32 + lane);
        float2 s0 = __half22float2(*reinterpret_cast<__half2*>(&s.x));
        float2 s1 = __half22float2(*reinterpret_cast<__half2*>(&s.y));
        acc[0] = 2.0f * acc[0] - s0.x;
        acc[1] = 2.0f * acc[1] - s0.y;
        acc[2] = 2.0f * acc[2] - s1.x;
        acc[3] = 2.0f * acc[3] - s1.y;
    }
    uint2 o;
    o.x = packh2(acc[0], acc[1]);
    o.y = packh2(acc[2], acc[3]);
    *((uint2*)g_Thalf + (size_t)node * 128 + yseg * 32 + lane) = o;
}

// ------------------------- layer-1 GEMM (12 x 128) -------------------------
__global__ void __launch_bounds__(256) k_gemm1(const float* __restrict__ W1,
                                               const float* __restrict__ b1) {
    __shared__ float shW[12 * 128];
    __shared__ float shT[32 * 12];
    int tid = threadIdx.x;
    for (int i = tid; i < 1536; i += 256) shW[i] = W1[i];
    int r0 = blockIdx.x * 32;
    for (int i = tid; i < 384; i += 256) {
        int r = i / 12, j = i % 12;
        int k = j / 3, d = j % 3;
        int gr = r0 + r;
        float v = 0.0f;
        if (gr < NN) {
            const float* src = (k == 0) ? g_t0 : (k == 1) ? g_t1 : (k == 2) ? g_t2 : g_t3;
            v = src[gr * 4 + d];
        }
        shT[i] = v;
    }
    __syncthreads();
    int r = tid >> 3;
    int c0 = (tid & 7) * 16;
    int gr = r0 + r;
    if (gr < NN) {
        #pragma unroll
        for (int c = c0; c < c0 + 16; c++) {
            float acc = b1[c];
            #pragma unroll
            for (int j = 0; j < 12; j++) acc = fmaf(shT[r * 12 + j], shW[j * 128 + c], acc);
            g_H[(size_t)gr * 128 + c] = acc;
        }
    }
}

// ------------------------- weight prep -------------------------
__global__ void k_prepw(const float* __restrict__ W, int widx) {
    int i = blockIdx.x * 256 + threadIdx.x;
    if (i < 512 * 64) {
        int k = i >> 6, np = i & 63;
        float x0 = W[k * 128 + 2 * np];
        float x1 = W[k * 128 + 2 * np + 1];
        uint32_t hi, lo;
        split2h(x0, x1, hi, lo);
        g_Wfhi[widx * 512 * 64 + i] = hi;
        g_Wflo[widx * 512 * 64 + i] = lo;
    }
}

// ------------------------- fp16 2-term ldmatrix GEMM, 3-stage pipeline ---------------------
// act >= 0 : write fp32 H + fused BN stats (partials)
// act == -2: layer-4 path — fused L2-norm + head, writes out directly (no H store)
#define AST 20
#define BSTU 68
#define A_UINTS (128 * AST)
#define B_UINTS (32 * BSTU)
#define STAGE_UINTS (A_UINTS + 2 * B_UINTS)
#define SMEM_GEMM (3 * STAGE_UINTS * 4)
#define TILE_ST 132

__global__ void __launch_bounds__(256, 2) k_gemm_f16(const float* __restrict__ bias,
                                                     int widx, int act,
                                                     const float* __restrict__ Wrep,
                                                     const float* __restrict__ brep,
                                                     float* __restrict__ out) {
    extern __shared__ uint32_t sm[];
    const int tid = threadIdx.x;
    const int lane = tid & 31;
    const int wid = tid >> 5;
    const int wm = wid & 3;
    const int wn = wid >> 2;
    const int lk = lane & 3;
    const int lr = lane >> 2;
    const int row0 = blockIdx.x * 128;
    const uint32_t sbase = smem_u32(sm);
    const uint32_t* Whi = g_Wfhi + widx * 512 * 64;
    const uint32_t* Wlo = g_Wflo + widx * 512 * 64;

    float acc[2][8][4];
    #pragma unroll
    for (int mt = 0; mt < 2; mt++)
        #pragma unroll
        for (int nt = 0; nt < 8; nt++)
            #pragma unroll
            for (int q = 0; q < 4; q++) acc[mt][nt][q] = 0.0f;

    const int laneRow = lane & 15;
    const int laneHi = lane >> 4;
    const uint32_t aLaneOff = (uint32_t)((wm * 32 + laneRow) * 80 + laneHi * 16);
    const uint32_t bLaneOff = (uint32_t)(laneRow * 272 + (wn * 64 + laneHi * 8) * 2);

    auto issue = [&](int c, int stage) {
        uint32_t Ab  = sbase + stage * STAGE_UINTS * 4;
        uint32_t Bhb = Ab + A_UINTS * 4;
        uint32_t Blb = Bhb + B_UINTS * 4;
        int auoff = (c >> 2) * 64 + (c & 3) * 16;
        #pragma unroll
        for (int j = 0; j < 2; j++) {
            int q = tid * 2 + j;
            int r = q >> 2, s4 = (q & 3) * 4;
            cp16(Ab + (r * AST + s4) * 4,
                 g_Thalf + (size_t)(row0 + r) * 256 + auoff + s4);
        }
        int kb = c * 32;
        #pragma unroll
        for (int j = 0; j < 2; j++) {
            int q = tid * 2 + j;
            int kr = q >> 4, n4 = (q & 15) * 4;
            cp16(Bhb + (kr * BSTU + n4) * 4, Whi + (kb + kr) * 64 + n4);
            cp16(Blb + (kr * BSTU + n4) * 4, Wlo + (kb + kr) * 64 + n4);
        }
        asm volatile("cp.async.commit_group;" ::: "memory");
    };

    issue(0, 0);
    issue(1, 1);

    for (int c = 0; c < 16; c++) {
        asm volatile("cp.async.wait_group 1;" ::: "memory");
        __syncthreads();
        if (c + 2 < 16)
            issue(c + 2, (c + 2) % 3);
        {
            uint32_t Ab = sbase + (c % 3) * STAGE_UINTS * 4;
            uint32_t Bb = Ab + A_UINTS * 4;
            #pragma unroll
            for (int ks = 0; ks < 2; ks++) {
                uint32_t a[2][4];
                #pragma unroll
                for (int mt = 0; mt < 2; mt++) {
                    uint32_t addr = Ab + aLaneOff + (uint32_t)(mt * 16 * 80 + ks * 32);
                    LDSM4(a[mt][0], a[mt][1], a[mt][2], a[mt][3], addr);
                }
                #pragma unroll
                for (int ntp = 0; ntp < 4; ntp++) {
                    uint32_t baddr = Bb + bLaneOff + (uint32_t)(ks * 16 * 272 + ntp * 32);
                    uint32_t h0, h1, h2, h3;
                    LDSM4T(h0, h1, h2, h3, baddr);
                    MMAF16(acc[0][2 * ntp],     a[0], h0, h1);
                    MMAF16(acc[1][2 * ntp],     a[1], h0, h1);
                    MMAF16(acc[0][2 * ntp + 1], a[0], h2, h3);
                    MMAF16(acc[1][2 * ntp + 1], a[1], h2, h3);
                    uint32_t l0, l1, l2, l3;
                    LDSM4T(l0, l1, l2, l3, baddr + B_UINTS * 4);
                    MMAF16(acc[0][2 * ntp],     a[0], l0, l1);
                    MMAF16(acc[1][2 * ntp],     a[1], l0, l1);
                    MMAF16(acc[0][2 * ntp + 1], a[0], l2, l3);
                    MMAF16(acc[1][2 * ntp + 1], a[1], l2, l3);
                }
            }
        }
        __syncthreads();
    }

    const int r1b = row0 + wm * 32 + lr;

    if (act != -2) {
        // ---- standard epilogue: bias + fp32 store + fused BN stats ----
        #pragma unroll
        for (int mt = 0; mt < 2; mt++) {
            int r1 = r1b + mt * 16;
            int r2 = r1 + 8;
            #pragma unroll
            for (int nt = 0; nt < 8; nt++) {
                int col = wn * 64 + nt * 8 + 2 * lk;
                float2 bs = *(const float2*)&bias[col];
                acc[mt][nt][0] += bs.x; acc[mt][nt][1] += bs.y;
                acc[mt][nt][2] += bs.x; acc[mt][nt][3] += bs.y;
                if (r1 < NN)
                    *(float2*)&g_H[(size_t)r1 * 128 + col] = make_float2(acc[mt][nt][0], acc[mt][nt][1]);
                if (r2 < NN)
                    *(float2*)&g_H[(size_t)r2 * 128 + col] = make_float2(acc[mt][nt][2], acc[mt][nt][3]);
            }
        }

        if (act >= 0) {
            float* sred = (float*)sm;
            __syncthreads();
            #pragma unroll
            for (int nt = 0; nt < 8; nt++) {
                float s0 = 0, s1 = 0, q0 = 0, q1 = 0;
                #pragma unroll
                for (int mt = 0; mt < 2; mt++) {
                    int r1 = r1b + mt * 16;
                    int r2 = r1 + 8;
                    if (r1 < NN) {
                        float v0 = apply_act(acc[mt][nt][0], act);
                        float v1 = apply_act(acc[mt][nt][1], act);
                        s0 += v0; q0 = fmaf(v0, v0, q0);
                        s1 += v1; q1 = fmaf(v1, v1, q1);
                    }
                    if (r2 < NN) {
                        float v0 = apply_act(acc[mt][nt][2], act);
                        float v1 = apply_act(acc[mt][nt][3], act);
                        s0 += v0; q0 = fmaf(v0, v0, q0);
                        s1 += v1; q1 = fmaf(v1, v1, q1);
                    }
                }
                #pragma unroll
                for (int o = 4; o < 32; o <<= 1) {
                    s0 += __shfl_xor_sync(0xFFFFFFFFu, s0, o);
                    s1 += __shfl_xor_sync(0xFFFFFFFFu, s1, o);
                    q0 += __shfl_xor_sync(0xFFFFFFFFu, q0, o);
                    q1 += __shfl_xor_sync(0xFFFFFFFFu, q1, o);
                }
                if (lr == 0) {
                    int col = wn * 64 + nt * 8 + 2 * lk;
                    sred[wm * 256 + col] = s0;
                    sred[wm * 256 + col + 1] = s1;
                    sred[wm * 256 + 128 + col] = q0;
                    sred[wm * 256 + 128 + col + 1] = q1;
                }
            }
            __syncthreads();
            g_part[blockIdx.x * 256 + tid] =
                sred[tid] + sred[256 + tid] + sred[512 + tid] + sred[768 + tid];
        }
    } else {
        // ---- layer-4 fused final: stage tile to smem, L2-norm + head, write out ----
        float* tile = (float*)sm;                    // 128 x TILE_ST floats
        float* wsh = tile + 128 * TILE_ST;           // 384 floats (Wrep)
        __syncthreads();                             // stage smem free now
        #pragma unroll
        for (int mt = 0; mt < 2; mt++) {
            int l1 = wm * 32 + mt * 16 + lr;
            int l2 = l1 + 8;
            #pragma unroll
            for (int nt = 0; nt < 8; nt++) {
                int col = wn * 64 + nt * 8 + 2 * lk;
                float2 bs = *(const float2*)&bias[col];
                *(float2*)&tile[l1 * TILE_ST + col] =
                    make_float2(acc[mt][nt][0] + bs.x, acc[mt][nt][1] + bs.y);
                *(float2*)&tile[l2 * TILE_ST + col] =
                    make_float2(acc[mt][nt][2] + bs.x, acc[mt][nt][3] + bs.y);
            }
        }
        for (int i = tid; i < 384; i += 256) wsh[i] = Wrep[i];
        __syncthreads();
        float br0 = brep[0], br1 = brep[1], br2 = brep[2];
        for (int rr = 0; rr < 16; rr++) {
            int lrow = wid * 16 + rr;
            int node = row0 + lrow;
            float4 h = *(const float4*)&tile[lrow * TILE_ST + lane * 4];
            float hv[4] = {h.x, h.y, h.z, h.w};
            float ss = 0.0f, p0 = 0.0f, p1 = 0.0f, p2 = 0.0f;
            #pragma unroll
            for (int q = 0; q < 4; q++) {
                int f = lane * 4 + q;
                ss = fmaf(hv[q], hv[q], ss);
                p0 = fmaf(hv[q], wsh[f * 3 + 0], p0);
                p1 = fmaf(hv[q], wsh[f * 3 + 1], p1);
                p2 = fmaf(hv[q], wsh[f * 3 + 2], p2);
            }
            #pragma unroll
            for (int o = 16; o > 0; o >>= 1) {
                ss += __shfl_xor_sync(0xFFFFFFFFu, ss, o);
                p0 += __shfl_xor_sync(0xFFFFFFFFu, p0, o);
                p1 += __shfl_xor_sync(0xFFFFFFFFu, p1, o);
                p2 += __shfl_xor_sync(0xFFFFFFFFu, p2, o);
            }
            if (lane == 0 && node < NN) {
                float inv = 1.0f / fmaxf(sqrtf(ss), L2_EPS);
                out[node * 3 + 0] = fmaf(p0, inv, br0);
                out[node * 3 + 1] = fmaf(p1, inv, br1);
                out[node * 3 + 2] = fmaf(p2, inv, br2);
            }
        }
    }
}

// ------------------------- layer-1 column stats (strided) -------------------------
__global__ void __launch_bounds__(128) k_colstat1(int act) {
    int c = threadIdx.x;
    float s = 0.0f, s2 = 0.0f;
    for (int r = blockIdx.x; r < NN; r += NPB) {
        float v = g_H[(size_t)r * 128 + c];
        v = apply_act(v, act);
        s += v;
        s2 = fmaf(v, v, s2);
    }
    g_part[blockIdx.x * 256 + c] = s;
    g_part[blockIdx.x * 256 + 128 + c] = s2;
}

// ------------------------- BN scale/shift from partials (wide) -------------------------
__global__ void __launch_bounds__(1024) k_colstat2(int nb,
                                                   const float* __restrict__ gamma,
                                                   const float* __restrict__ beta) {
    __shared__ float red[1024];
    int e = threadIdx.x & 255;
    int ch = threadIdx.x >> 8;
    float s = 0.0f;
    for (int b = ch; b < nb; b += 4) s += g_part[b * 256 + e];
    red[threadIdx.x] = s;
    __syncthreads();
    if (threadIdx.x < 256) {
        red[threadIdx.x] = red[threadIdx.x] + red[threadIdx.x + 256]
                         + red[threadIdx.x + 512] + red[threadIdx.x + 768];
    }
    __syncthreads();
    if (threadIdx.x < 128) {
        int c = threadIdx.x;
        float sm_ = red[c];
        float s2 = red[c + 128];
        float mu = sm_ / (float)NN;
        float var = s2 / (float)NN - mu * mu;
        float sc = gamma[c] * rsqrtf(var + BN_EPS);
        g_scale[c] = sc;
        g_shift[c] = beta[c] - mu * sc;
    }
}

// float4 reads, uint2 writes
__global__ void __launch_bounds__(256) k_bnapply(int act) {
    int idx = blockIdx.x * blockDim.x + threadIdx.x;
    if (idx < NN * 32) {
        int p = idx & 31;
        int r = idx >> 5;
        int c = p * 4;
        float4 h0 = *(const float4*)&g_H[(size_t)r * 128 + c];
        float v0 = fmaf(apply_act(h0.x, act), g_scale[c],     g_shift[c]);
        float v1 = fmaf(apply_act(h0.y, act), g_scale[c + 1], g_shift[c + 1]);
        float v2 = fmaf(apply_act(h0.z, act), g_scale[c + 2], g_shift[c + 2]);
        float v3 = fmaf(apply_act(h0.w, act), g_scale[c + 3], g_shift[c + 3]);
        uint2 o;
        o.x = packh2(v0, v1);
        o.y = packh2(v2, v3);
        *((uint2*)g_Thalf + (size_t)r * 128 + p) = o;
    }
}

// ------------------------- host -------------------------
extern "C" void kernel_launch(void* const* d_in, const int* in_sizes, int n_in,
                              void* d_out, int out_size) {
    const float* x    = (const float*)d_in[0];
    const void*  ei   = d_in[1];
    const float* W1   = (const float*)d_in[2];
    const float* b1   = (const float*)d_in[3];
    const float* W2   = (const float*)d_in[4];
    const float* b2   = (const float*)d_in[5];
    const float* W3   = (const float*)d_in[6];
    const float* b3   = (const float*)d_in[7];
    const float* W4   = (const float*)d_in[8];
    const float* b4   = (const float*)d_in[9];
    const float* g1   = (const float*)d_in[10];
    const float* be1  = (const float*)d_in[11];
    const float* g2   = (const float*)d_in[12];
    const float* be2  = (const float*)d_in[13];
    const float* g3   = (const float*)d_in[14];
    const float* be3  = (const float*)d_in[15];
    const float* Wrep = (const float*)d_in[16];
    const float* brep = (const float*)d_in[17];
    float* out = (float*)d_out;

    int E = in_sizes[1] / 2;
    if (E > EE) E = EE;

    static int s_attr_done = 0;
    if (!s_attr_done) {
        cudaFuncSetAttribute(k_gemm_f16, cudaFuncAttributeMaxDynamicSharedMemorySize, SMEM_GEMM);
        s_attr_done = 1;
    }

    const int TB = 256;
    int gN = (NN + TB - 1) / TB;
    int gE = (E + TB - 1) / TB;
    int gW8 = (NN + 7) / 8;
    int gScan = (NN + 1 + 511) / 512;
    int gBN = (NN * 32 + TB - 1) / TB;

    // ---- graph structure + weight prep (front-loaded) ----
    k_detect<<<1, 32>>>((const int*)ei);
    k_prepw<<<128, 256>>>(W2, 0);
    k_prepw<<<128, 256>>>(W3, 1);
    k_prepw<<<128, 256>>>(W4, 2);
    k_init<<<gN, TB>>>(x);
    k_count<<<gE, TB>>>(ei, E);
    k_scan1<<<gScan, 512>>>();
    k_scan2<<<1, 1>>>(gScan);
    k_scan3<<<gScan, 512>>>();
    k_scatter<<<gE, TB>>>(ei, E);

    // ---- layer 1 (F=3) ----
    k_spmm3<<<gN, TB>>>(0, 1, -1);
    k_spmm3<<<gN, TB>>>(1, 2, 0);
    k_spmm3<<<gN, TB>>>(2, 3, 1);
    k_gemm1<<<(NN + 31) / 32, 256>>>(W1, b1);
    k_colstat1<<<NPB, 128>>>(0);
    k_colstat2<<<1, 1024>>>(NPB, g1, be1);
    k_bnapply<<<gBN, TB>>>(0);

    // ---- layer 2 ----
    k_spmm128w<<<gW8, 256>>>(0, 1, -1);
    k_spmm128w<<<gW8, 256>>>(1, 2, 0);
    k_spmm128w<<<gW8, 256>>>(2, 3, 1);
    k_gemm_f16<<<NPB, 256, SMEM_GEMM>>>(b2, 0, 0, Wrep, brep, out);
    k_colstat2<<<1, 1024>>>(NPB, g2, be2);
    k_bnapply<<<gBN, TB>>>(0);

    // ---- layer 3 ----
    k_spmm128w<<<gW8, 256>>>(0, 1, -1);
    k_spmm128w<<<gW8, 256>>>(1, 2, 0);
    k_spmm128w<<<gW8, 256>>>(2, 3, 1);
    k_gemm_f16<<<NPB, 256, SMEM_GEMM>>>(b3, 1, 1, Wrep, brep, out);
    k_colstat2<<<1, 1024>>>(NPB, g3, be3);
    k_bnapply<<<gBN, TB>>>(1);

    // ---- layer 4: GEMM with fused L2-norm + head ----
    k_spmm128w<<<gW8, 256>>>(0, 1, -1);
    k_spmm128w<<<gW8, 256>>>(1, 2, 0);
    k_spmm128w<<<gW8, 256>>>(2, 3, 1);
    k_gemm_f16<<<NPB, 256, SMEM_GEMM>>>(b4, 2, -2, Wrep, brep, out);
}

// round 16
// speedup vs baseline: 1.2372x; 1.0239x over previous
#include <cuda_runtime.h>
#include <cuda_bf16.h>
#include <cuda_fp16.h>
#include <math.h>
#include <stdint.h>

#define NN 100000
#define NN_PAD 100096
#define NPB (NN_PAD / 128)
#define EE 1600000
#define HID 128
#define NEG 0.01f
#define BN_EPS 1e-5f
#define L2_EPS 1e-12f
#define STSCALE 1048576.0f
#define INV_STSCALE (1.0f / 1048576.0f)

// ------------------------- device scratch -------------------------
__device__ uint32_t g_Thalf[(size_t)NN_PAD * 256]; // [T0|T1|T2|T3] fp16 packed, 64 half2/seg
__device__ float g_H[(size_t)NN * 128];            // GEMM output (pre-activation)
__device__ float g_t0[NN * 4];
__device__ float g_t1[NN * 4];
__device__ float g_t2[NN * 4];
__device__ float g_t3[NN * 4];
__device__ float g_dinv[NN];
__device__ int   g_indeg[NN];
__device__ int   g_ptr[NN + 1];
__device__ int   g_fill[NN];
__device__ int   g_bsums[256];
__device__ int2  g_edge[EE];
__device__ unsigned long long g_isum[3 * 256];     // fixed-point stats: [layer][0..127]=sum, [128..255]=sumsq
__device__ float g_scale[128];
__device__ float g_shift[128];
__device__ uint32_t g_Wfhi[3 * 512 * 64];
__device__ uint32_t g_Wflo[3 * 512 * 64];
__device__ int   g_is64;

// ------------------------- helpers -------------------------
__device__ __forceinline__ uint32_t smem_u32(const void* p) {
    uint32_t a;
    asm("{ .reg .u64 t; cvta.to.shared.u64 t, %1; cvt.u32.u64 %0, t; }" : "=r"(a) : "l"(p));
    return a;
}

__device__ __forceinline__ uint32_t packh2(float a, float b) {
    __half2 h = __floats2half2_rn(a, b);
    return *reinterpret_cast<uint32_t*>(&h);
}

__device__ __forceinline__ void split2h(float x0, float x1, uint32_t& hi, uint32_t& lo) {
    __half h0 = __float2half_rn(x0);
    __half h1 = __float2half_rn(x1);
    float r0 = x0 - __half2float(h0);
    float r1 = x1 - __half2float(h1);
    __half2 H; H.x = h0; H.y = h1;
    hi = *reinterpret_cast<uint32_t*>(&H);
    lo = packh2(r0, r1);
}

__device__ __forceinline__ void statadd(int buf, int idx, float v) {
    long long q = __float2ll_rn(v * STSCALE);
    atomicAdd(&g_isum[buf * 256 + idx], (unsigned long long)q);
}

#define MMAF16(c, a, b0, b1) \
    asm volatile("mma.sync.aligned.m16n8k16.row.col.f32.f16.f16.f32 " \
        "{%0,%1,%2,%3}, {%4,%5,%6,%7}, {%8,%9}, {%0,%1,%2,%3};" \
        : "+f"((c)[0]), "+f"((c)[1]), "+f"((c)[2]), "+f"((c)[3]) \
        : "r"((a)[0]), "r"((a)[1]), "r"((a)[2]), "r"((a)[3]), "r"(b0), "r"(b1))

#define LDSM4(r0, r1, r2, r3, a) \
    asm volatile("ldmatrix.sync.aligned.m8n8.x4.shared.b16 {%0,%1,%2,%3}, [%4];" \
        : "=r"(r0), "=r"(r1), "=r"(r2), "=r"(r3) : "r"(a))

#define LDSM4T(r0, r1, r2, r3, a) \
    asm volatile("ldmatrix.sync.aligned.m8n8.x4.trans.shared.b16 {%0,%1,%2,%3}, [%4];" \
        : "=r"(r0), "=r"(r1), "=r"(r2), "=r"(r3) : "r"(a))

__device__ __forceinline__ void cp16(uint32_t sdst, const void* gsrc) {
    asm volatile("cp.async.ca.shared.global [%0], [%1], 16;" :: "r"(sdst), "l"(gsrc) : "memory");
}

__device__ __forceinline__ void acc4(float* acc, uint2 v, float w) {
    float2 f0 = __half22float2(*reinterpret_cast<__half2*>(&v.x));
    float2 f1 = __half22float2(*reinterpret_cast<__half2*>(&v.y));
    acc[0] = fmaf(w, f0.x, acc[0]);
    acc[1] = fmaf(w, f0.y, acc[1]);
    acc[2] = fmaf(w, f1.x, acc[2]);
    acc[3] = fmaf(w, f1.y, acc[3]);
}

__device__ __forceinline__ float apply_act(float v, int act) {
    return act ? fmaxf(v, 0.0f) : (v >= 0.0f ? v : NEG * v);
}

// ------------------------- edge helpers -------------------------
__device__ __forceinline__ void load_edge(const void* ei, int E, int e, int& s, int& d) {
    if (g_is64) {
        const long long* p = (const long long*)ei;
        s = (int)p[e];
        d = (int)p[(size_t)E + e];
    } else {
        const int* p = (const int*)ei;
        s = p[e];
        d = p[E + e];
    }
}

// ------------------------- setup kernels -------------------------
__global__ void k_detect(const int* ei32) {
    if (threadIdx.x == 0 && blockIdx.x == 0) {
        int is64 = 1;
        for (int i = 0; i < 32; i++) {
            if (ei32[2 * i + 1] != 0) { is64 = 0; break; }
        }
        g_is64 = is64;
    }
}

__global__ void k_init(const float* __restrict__ x) {
    int i = blockIdx.x * blockDim.x + threadIdx.x;
    if (i < 768) g_isum[i] = 0ull;
    if (i < NN) {
        g_indeg[i] = 0;
        float4 v;
        v.x = x[3 * i];
        v.y = x[3 * i + 1];
        v.z = x[3 * i + 2];
        v.w = 0.0f;
        *(float4*)&g_t0[4 * i] = v;
    }
}

__global__ void k_count(const void* ei, int E) {
    int e = blockIdx.x * blockDim.x + threadIdx.x;
    if (e < E) {
        int s, d;
        load_edge(ei, E, e, s, d);
        atomicAdd(&g_indeg[d], 1);
    }
}

__global__ void k_scan1() {
    __shared__ int sh[512];
    int gid = blockIdx.x * 512 + threadIdx.x;
    int v = (gid < NN) ? g_indeg[gid] : 0;
    if (gid < NN) {
        float dg = (float)v;
        g_dinv[gid] = (dg > 0.0f) ? rsqrtf(fmaxf(dg, 1.0f)) : 0.0f;
    }
    sh[threadIdx.x] = v;
    __syncthreads();
    for (int off = 1; off < 512; off <<= 1) {
        int t = (threadIdx.x >= off) ? sh[threadIdx.x - off] : 0;
        __syncthreads();
        sh[threadIdx.x] += t;
        __syncthreads();
    }
    if (gid <= NN) g_ptr[gid] = sh[threadIdx.x] - v;
    if (threadIdx.x == 511) g_bsums[blockIdx.x] = sh[511];
}

__global__ void k_scan2(int nb) {
    if (threadIdx.x == 0 && blockIdx.x == 0) {
        int acc = 0;
        for (int i = 0; i < nb; i++) { int t = g_bsums[i]; g_bsums[i] = acc; acc += t; }
    }
}

__global__ void k_scan3() {
    int gid = blockIdx.x * 512 + threadIdx.x;
    if (gid <= NN) {
        int p = g_ptr[gid] + g_bsums[blockIdx.x];
        g_ptr[gid] = p;
        if (gid < NN) g_fill[gid] = p;
    }
}

__global__ void k_scatter(const void* ei, int E) {
    int e = blockIdx.x * blockDim.x + threadIdx.x;
    if (e < E) {
        int s, d;
        load_edge(ei, E, e, s, d);
        float w = -(g_dinv[s] * g_dinv[d]);
        int pos = atomicAdd(&g_fill[d], 1);
        g_edge[pos] = make_int2(s, __float_as_int(w));
    }
}

// ------------------------- layer-1 sparse (F=3, float4 rows) -------------------------
__global__ void k_spmm3(int xc, int yc, int subc) {
    int i = blockIdx.x * blockDim.x + threadIdx.x;
    if (i >= NN) return;
    const float4* X = (const float4*)((xc == 0) ? g_t0 : (xc == 1) ? g_t1 : (xc == 2) ? g_t2 : g_t3);
    float4*       Y = (float4*)((yc == 1) ? g_t1 : (yc == 2) ? g_t2 : g_t3);
    int b = g_ptr[i], en = g_ptr[i + 1];
    float a0 = 0, a1 = 0, a2 = 0;
    int e = b;
    for (; e + 4 <= en; e += 4) {
        int2 e0 = __ldg(&g_edge[e]);
        int2 e1 = __ldg(&g_edge[e + 1]);
        int2 e2 = __ldg(&g_edge[e + 2]);
        int2 e3 = __ldg(&g_edge[e + 3]);
        float4 v0 = __ldg(&X[e0.x]);
        float4 v1 = __ldg(&X[e1.x]);
        float4 v2 = __ldg(&X[e2.x]);
        float4 v3 = __ldg(&X[e3.x]);
        float w0 = __int_as_float(e0.y), w1 = __int_as_float(e1.y);
        float w2 = __int_as_float(e2.y), w3 = __int_as_float(e3.y);
        a0 = fmaf(w0, v0.x, a0); a1 = fmaf(w0, v0.y, a1); a2 = fmaf(w0, v0.z, a2);
        a0 = fmaf(w1, v1.x, a0); a1 = fmaf(w1, v1.y, a1); a2 = fmaf(w1, v1.z, a2);
        a0 = fmaf(w2, v2.x, a0); a1 = fmaf(w2, v2.y, a1); a2 = fmaf(w2, v2.z, a2);
        a0 = fmaf(w3, v3.x, a0); a1 = fmaf(w3, v3.y, a1); a2 = fmaf(w3, v3.z, a2);
    }
    for (; e < en; e++) {
        int2 ed = __ldg(&g_edge[e]);
        float ww = __int_as_float(ed.y);
        float4 v = __ldg(&X[ed.x]);
        a0 = fmaf(ww, v.x, a0);
        a1 = fmaf(ww, v.y, a1);
        a2 = fmaf(ww, v.z, a2);
    }
    float4 o;
    if (subc < 0) {
        o = make_float4(a0, a1, a2, 0.0f);
    } else {
        const float4* S = (const float4*)((subc == 0) ? g_t0 : (subc == 1) ? g_t1 : (subc == 2) ? g_t2 : g_t3);
        float4 s = S[i];
        o = make_float4(2.0f * a0 - s.x, 2.0f * a1 - s.y, 2.0f * a2 - s.z, 0.0f);
    }
    Y[i] = o;
}

// ------------------------- F=128 SpMM: warp per node, fp16 in/out (frozen) -----------------
__global__ void __launch_bounds__(256) k_spmm128w(int xseg, int yseg, int subseg) {
    int node = blockIdx.x * 8 + (threadIdx.x >> 5);
    if (node >= NN) return;
    int lane = threadIdx.x & 31;
    int b = g_ptr[node], en = g_ptr[node + 1];
    float acc[4] = {0, 0, 0, 0};
    const uint2* Xb = (const uint2*)g_Thalf;
    const uint32_t xo = xseg * 32 + lane;

    int e = b;
    for (; e + 4 <= en; e += 4) {
        int2 e0 = __ldg(&g_edge[e]);
        int2 e1 = __ldg(&g_edge[e + 1]);
        int2 e2 = __ldg(&g_edge[e + 2]);
        int2 e3 = __ldg(&g_edge[e + 3]);
        uint2 v0 = __ldg(&Xb[(size_t)e0.x * 128 + xo]);
        uint2 v1 = __ldg(&Xb[(size_t)e1.x * 128 + xo]);
        uint2 v2 = __ldg(&Xb[(size_t)e2.x * 128 + xo]);
        uint2 v3 = __ldg(&Xb[(size_t)e3.x * 128 + xo]);
        acc4(acc, v0, __int_as_float(e0.y));
        acc4(acc, v1, __int_as_float(e1.y));
        acc4(acc, v2, __int_as_float(e2.y));
        acc4(acc, v3, __int_as_float(e3.y));
    }
    for (; e < en; e++) {
        int2 ed = __ldg(&g_edge[e]);
        uint2 v = __ldg(&Xb[(size_t)ed.x * 128 + xo]);
        acc4(acc, v, __int_as_float(ed.y));
    }

    if (subseg >= 0) {
        uint2 s = __ldg((const uint2*)g_Thalf + (size_t)node * 128 + subseg * 32 + lane);
        float2 s0 = __half22float2(*reinterpret_cast<__half2*>(&s.x));
        float2 s1 = __half22float2(*reinterpret_cast<__half2*>(&s.y));
        acc[0] = 2.0f * acc[0] - s0.x;
        acc[1] = 2.0f * acc[1] - s0.y;
        acc[2] = 2.0f * acc[2] - s1.x;
        acc[3] = 2.0f * acc[3] - s1.y;
    }
    uint2 o;
    o.x = packh2(acc[0], acc[1]);
    o.y = packh2(acc[2], acc[3]);
    *((uint2*)g_Thalf + (size_t)node * 128 + yseg * 32 + lane) = o;
}

// ------------------------- layer-1 GEMM (12 x 128) + fused stats (buf 0, leaky) ------------
__global__ void __launch_bounds__(256) k_gemm1(const float* __restrict__ W1,
                                               const float* __restrict__ b1) {
    __shared__ float shW[12 * 128];
    __shared__ float shT[32 * 12];
    __shared__ float sred[32 * 128];
    int tid = threadIdx.x;
    for (int i = tid; i < 1536; i += 256) shW[i] = W1[i];
    int r0 = blockIdx.x * 32;
    for (int i = tid; i < 384; i += 256) {
        int r = i / 12, j = i % 12;
        int k = j / 3, d = j % 3;
        int gr = r0 + r;
        float v = 0.0f;
        if (gr < NN) {
            const float* src = (k == 0) ? g_t0 : (k == 1) ? g_t1 : (k == 2) ? g_t2 : g_t3;
            v = src[gr * 4 + d];
        }
        shT[i] = v;
    }
    __syncthreads();
    int r = tid >> 3;
    int c0 = (tid & 7) * 16;
    int gr = r0 + r;
    if (gr < NN) {
        #pragma unroll
        for (int c = c0; c < c0 + 16; c++) {
            float acc = b1[c];
            #pragma unroll
            for (int j = 0; j < 12; j++) acc = fmaf(shT[r * 12 + j], shW[j * 128 + c], acc);
            g_H[(size_t)gr * 128 + c] = acc;
            sred[r * 128 + c] = apply_act(acc, 0);
        }
    } else {
        #pragma unroll
        for (int c = c0; c < c0 + 16; c++) sred[r * 128 + c] = 0.0f;
    }
    __syncthreads();
    if (tid < 128) {
        float s = 0.0f, q = 0.0f;
        #pragma unroll 8
        for (int rr = 0; rr < 32; rr++) {
            float v = sred[rr * 128 + tid];
            s += v;
            q = fmaf(v, v, q);
        }
        statadd(0, tid, s);
        statadd(0, 128 + tid, q);
    }
}

// ------------------------- weight prep (single launch, 3 weights) --------------------------
__global__ void k_prepw(const float* __restrict__ W2, const float* __restrict__ W3,
                        const float* __restrict__ W4) {
    int widx = blockIdx.x >> 7;
    const float* W = (widx == 0) ? W2 : (widx == 1) ? W3 : W4;
    int i = (blockIdx.x & 127) * 256 + threadIdx.x;
    if (i < 512 * 64) {
        int k = i >> 6, np = i & 63;
        float x0 = W[k * 128 + 2 * np];
        float x1 = W[k * 128 + 2 * np + 1];
        uint32_t hi, lo;
        split2h(x0, x1, hi, lo);
        g_Wfhi[widx * 512 * 64 + i] = hi;
        g_Wflo[widx * 512 * 64 + i] = lo;
    }
}

// ------------------------- fp16 2-term ldmatrix GEMM, 3-stage pipeline ---------------------
// act >= 0 : fp32 H store + fused BN stats into g_isum[widx+1]
// act == -2: layer-4 path — fused L2-norm + head, writes out directly
#define AST 20
#define BSTU 68
#define A_UINTS (128 * AST)
#define B_UINTS (32 * BSTU)
#define STAGE_UINTS (A_UINTS + 2 * B_UINTS)
#define SMEM_GEMM (3 * STAGE_UINTS * 4)
#define TILE_ST 132

__global__ void __launch_bounds__(256, 2) k_gemm_f16(const float* __restrict__ bias,
                                                     int widx, int act,
                                                     const float* __restrict__ Wrep,
                                                     const float* __restrict__ brep,
                                                     float* __restrict__ out) {
    extern __shared__ uint32_t sm[];
    const int tid = threadIdx.x;
    const int lane = tid & 31;
    const int wid = tid >> 5;
    const int wm = wid & 3;
    const int wn = wid >> 2;
    const int lk = lane & 3;
    const int lr = lane >> 2;
    const int row0 = blockIdx.x * 128;
    const uint32_t sbase = smem_u32(sm);
    const uint32_t* Whi = g_Wfhi + widx * 512 * 64;
    const uint32_t* Wlo = g_Wflo + widx * 512 * 64;

    float acc[2][8][4];
    #pragma unroll
    for (int mt = 0; mt < 2; mt++)
        #pragma unroll
        for (int nt = 0; nt < 8; nt++)
            #pragma unroll
            for (int q = 0; q < 4; q++) acc[mt][nt][q] = 0.0f;

    const int laneRow = lane & 15;
    const int laneHi = lane >> 4;
    const uint32_t aLaneOff = (uint32_t)((wm * 32 + laneRow) * 80 + laneHi * 16);
    const uint32_t bLaneOff = (uint32_t)(laneRow * 272 + (wn * 64 + laneHi * 8) * 2);

    auto issue = [&](int c, int stage) {
        uint32_t Ab  = sbase + stage * STAGE_UINTS * 4;
        uint32_t Bhb = Ab + A_UINTS * 4;
        uint32_t Blb = Bhb + B_UINTS * 4;
        int auoff = (c >> 2) * 64 + (c & 3) * 16;
        #pragma unroll
        for (int j = 0; j < 2; j++) {
            int q = tid * 2 + j;
            int r = q >> 2, s4 = (q & 3) * 4;
            cp16(Ab + (r * AST + s4) * 4,
                 g_Thalf + (size_t)(row0 + r) * 256 + auoff + s4);
        }
        int kb = c * 32;
        #pragma unroll
        for (int j = 0; j < 2; j++) {
            int q = tid * 2 + j;
            int kr = q >> 4, n4 = (q & 15) * 4;
            cp16(Bhb + (kr * BSTU + n4) * 4, Whi + (kb + kr) * 64 + n4);
            cp16(Blb + (kr * BSTU + n4) * 4, Wlo + (kb + kr) * 64 + n4);
        }
        asm volatile("cp.async.commit_group;" ::: "memory");
    };

    issue(0, 0);
    issue(1, 1);

    for (int c = 0; c < 16; c++) {
        asm volatile("cp.async.wait_group 1;" ::: "memory");
        __syncthreads();
        if (c + 2 < 16)
            issue(c + 2, (c + 2) % 3);
        {
            uint32_t Ab = sbase + (c % 3) * STAGE_UINTS * 4;
            uint32_t Bb = Ab + A_UINTS * 4;
            #pragma unroll
            for (int ks = 0; ks < 2; ks++) {
                uint32_t a[2][4];
                #pragma unroll
                for (int mt = 0; mt < 2; mt++) {
                    uint32_t addr = Ab + aLaneOff + (uint32_t)(mt * 16 * 80 + ks * 32);
                    LDSM4(a[mt][0], a[mt][1], a[mt][2], a[mt][3], addr);
                }
                #pragma unroll
                for (int ntp = 0; ntp < 4; ntp++) {
                    uint32_t baddr = Bb + bLaneOff + (uint32_t)(ks * 16 * 272 + ntp * 32);
                    uint32_t h0, h1, h2, h3;
                    LDSM4T(h0, h1, h2, h3, baddr);
                    MMAF16(acc[0][2 * ntp],     a[0], h0, h1);
                    MMAF16(acc[1][2 * ntp],     a[1], h0, h1);
                    MMAF16(acc[0][2 * ntp + 1], a[0], h2, h3);
                    MMAF16(acc[1][2 * ntp + 1], a[1], h2, h3);
                    uint32_t l0, l1, l2, l3;
                    LDSM4T(l0, l1, l2, l3, baddr + B_UINTS * 4);
                    MMAF16(acc[0][2 * ntp],     a[0], l0, l1);
                    MMAF16(acc[1][2 * ntp],     a[1], l0, l1);
                    MMAF16(acc[0][2 * ntp + 1], a[0], l2, l3);
                    MMAF16(acc[1][2 * ntp + 1], a[1], l2, l3);
                }
            }
        }
        __syncthreads();
    }

    const int r1b = row0 + wm * 32 + lr;

    if (act != -2) {
        #pragma unroll
        for (int mt = 0; mt < 2; mt++) {
            int r1 = r1b + mt * 16;
            int r2 = r1 + 8;
            #pragma unroll
            for (int nt = 0; nt < 8; nt++) {
                int col = wn * 64 + nt * 8 + 2 * lk;
                float2 bs = *(const float2*)&bias[col];
                acc[mt][nt][0] += bs.x; acc[mt][nt][1] += bs.y;
                acc[mt][nt][2] += bs.x; acc[mt][nt][3] += bs.y;
                if (r1 < NN)
                    *(float2*)&g_H[(size_t)r1 * 128 + col] = make_float2(acc[mt][nt][0], acc[mt][nt][1]);
                if (r2 < NN)
                    *(float2*)&g_H[(size_t)r2 * 128 + col] = make_float2(acc[mt][nt][2], acc[mt][nt][3]);
            }
        }

        if (act >= 0) {
            float* sred = (float*)sm;
            __syncthreads();
            #pragma unroll
            for (int nt = 0; nt < 8; nt++) {
                float s0 = 0, s1 = 0, q0 = 0, q1 = 0;
                #pragma unroll
                for (int mt = 0; mt < 2; mt++) {
                    int r1 = r1b + mt * 16;
                    int r2 = r1 + 8;
                    if (r1 < NN) {
                        float v0 = apply_act(acc[mt][nt][0], act);
                        float v1 = apply_act(acc[mt][nt][1], act);
                        s0 += v0; q0 = fmaf(v0, v0, q0);
                        s1 += v1; q1 = fmaf(v1, v1, q1);
                    }
                    if (r2 < NN) {
                        float v0 = apply_act(acc[mt][nt][2], act);
                        float v1 = apply_act(acc[mt][nt][3], act);
                        s0 += v0; q0 = fmaf(v0, v0, q0);
                        s1 += v1; q1 = fmaf(v1, v1, q1);
                    }
                }
                #pragma unroll
                for (int o = 4; o < 32; o <<= 1) {
                    s0 += __shfl_xor_sync(0xFFFFFFFFu, s0, o);
                    s1 += __shfl_xor_sync(0xFFFFFFFFu, s1, o);
                    q0 += __shfl_xor_sync(0xFFFFFFFFu, q0, o);
                    q1 += __shfl_xor_sync(0xFFFFFFFFu, q1, o);
                }
                if (lr == 0) {
                    int col = wn * 64 + nt * 8 + 2 * lk;
                    sred[wm * 256 + col] = s0;
                    sred[wm * 256 + col + 1] = s1;
                    sred[wm * 256 + 128 + col] = q0;
                    sred[wm * 256 + 128 + col + 1] = q1;
                }
            }
            __syncthreads();
            float v = sred[tid] + sred[256 + tid] + sred[512 + tid] + sred[768 + tid];
            statadd(widx + 1, tid, v);
        }
    } else {
        float* tile = (float*)sm;
        float* wsh = tile + 128 * TILE_ST;
        __syncthreads();
        #pragma unroll
        for (int mt = 0; mt < 2; mt++) {
            int l1 = wm * 32 + mt * 16 + lr;
            int l2 = l1 + 8;
            #pragma unroll
            for (int nt = 0; nt < 8; nt++) {
                int col = wn * 64 + nt * 8 + 2 * lk;
                float2 bs = *(const float2*)&bias[col];
                *(float2*)&tile[l1 * TILE_ST + col] =
                    make_float2(acc[mt][nt][0] + bs.x, acc[mt][nt][1] + bs.y);
                *(float2*)&tile[l2 * TILE_ST + col] =
                    make_float2(acc[mt][nt][2] + bs.x, acc[mt][nt][3] + bs.y);
            }
        }
        for (int i = tid; i < 384; i += 256) wsh[i] = Wrep[i];
        __syncthreads();
        float br0 = brep[0], br1 = brep[1], br2 = brep[2];
        for (int rr = 0; rr < 16; rr++) {
            int lrow = wid * 16 + rr;
            int node = row0 + lrow;
            float4 h = *(const float4*)&tile[lrow * TILE_ST + lane * 4];
            float hv[4] = {h.x, h.y, h.z, h.w};
            float ss = 0.0f, p0 = 0.0f, p1 = 0.0f, p2 = 0.0f;
            #pragma unroll
            for (int q = 0; q < 4; q++) {
                int f = lane * 4 + q;
                ss = fmaf(hv[q], hv[q], ss);
                p0 = fmaf(hv[q], wsh[f * 3 + 0], p0);
                p1 = fmaf(hv[q], wsh[f * 3 + 1], p1);
                p2 = fmaf(hv[q], wsh[f * 3 + 2], p2);
            }
            #pragma unroll
            for (int o = 16; o > 0; o >>= 1) {
                ss += __shfl_xor_sync(0xFFFFFFFFu, ss, o);
                p0 += __shfl_xor_sync(0xFFFFFFFFu, p0, o);
                p1 += __shfl_xor_sync(0xFFFFFFFFu, p1, o);
                p2 += __shfl_xor_sync(0xFFFFFFFFu, p2, o);
            }
            if (lane == 0 && node < NN) {
                float inv = 1.0f / fmaxf(sqrtf(ss), L2_EPS);
                out[node * 3 + 0] = fmaf(p0, inv, br0);
                out[node * 3 + 1] = fmaf(p1, inv, br1);
                out[node * 3 + 2] = fmaf(p2, inv, br2);
            }
        }
    }
}

// ------------------------- BN apply: per-block scale/shift from int64 stats ----------------
__global__ void __launch_bounds__(256) k_bnapply(int buf, int act,
                                                 const float* __restrict__ gamma,
                                                 const float* __restrict__ beta) {
    __shared__ float ssc[128], ssh[128];
    int tid = threadIdx.x;
    if (tid < 128) {
        float s  = (float)((long long)g_isum[buf * 256 + tid]) * INV_STSCALE;
        float s2 = (float)((long long)g_isum[buf * 256 + 128 + tid]) * INV_STSCALE;
        float mu = s / (float)NN;
        float var = s2 / (float)NN - mu * mu;
        float sc = gamma[tid] * rsqrtf(var + BN_EPS);
        ssc[tid] = sc;
        ssh[tid] = beta[tid] - mu * sc;
    }
    __syncthreads();
    int idx = blockIdx.x * blockDim.x + tid;
    if (idx < NN * 32) {
        int p = idx & 31;
        int r = idx >> 5;
        int c = p * 4;
        float4 h0 = *(const float4*)&g_H[(size_t)r * 128 + c];
        float v0 = fmaf(apply_act(h0.x, act), ssc[c],     ssh[c]);
        float v1 = fmaf(apply_act(h0.y, act), ssc[c + 1], ssh[c + 1]);
        float v2 = fmaf(apply_act(h0.z, act), ssc[c + 2], ssh[c + 2]);
        float v3 = fmaf(apply_act(h0.w, act), ssc[c + 3], ssh[c + 3]);
        uint2 o;
        o.x = packh2(v0, v1);
        o.y = packh2(v2, v3);
        *((uint2*)g_Thalf + (size_t)r * 128 + p) = o;
    }
}

// ------------------------- host -------------------------
extern "C" void kernel_launch(void* const* d_in, const int* in_sizes, int n_in,
                              void* d_out, int out_size) {
    const float* x    = (const float*)d_in[0];
    const void*  ei   = d_in[1];
    const float* W1   = (const float*)d_in[2];
    const float* b1   = (const float*)d_in[3];
    const float* W2   = (const float*)d_in[4];
    const float* b2   = (const float*)d_in[5];
    const float* W3   = (const float*)d_in[6];
    const float* b3   = (const float*)d_in[7];
    const float* W4   = (const float*)d_in[8];
    const float* b4   = (const float*)d_in[9];
    const float* g1   = (const float*)d_in[10];
    const float* be1  = (const float*)d_in[11];
    const float* g2   = (const float*)d_in[12];
    const float* be2  = (const float*)d_in[13];
    const float* g3   = (const float*)d_in[14];
    const float* be3  = (const float*)d_in[15];
    const float* Wrep = (const float*)d_in[16];
    const float* brep = (const float*)d_in[17];
    float* out = (float*)d_out;

    int E = in_sizes[1] / 2;
    if (E > EE) E = EE;

    static int s_attr_done = 0;
    if (!s_attr_done) {
        cudaFuncSetAttribute(k_gemm_f16, cudaFuncAttributeMaxDynamicSharedMemorySize, SMEM_GEMM);
        s_attr_done = 1;
    }

    const int TB = 256;
    int gN = (NN + TB - 1) / TB;
    int gE = (E + TB - 1) / TB;
    int gW8 = (NN + 7) / 8;
    int gScan = (NN + 1 + 511) / 512;
    int gBN = (NN * 32 + TB - 1) / TB;

    // ---- graph structure + weight prep ----
    k_detect<<<1, 32>>>((const int*)ei);
    k_prepw<<<384, 256>>>(W2, W3, W4);
    k_init<<<gN, TB>>>(x);
    k_count<<<gE, TB>>>(ei, E);
    k_scan1<<<gScan, 512>>>();
    k_scan2<<<1, 1>>>(gScan);
    k_scan3<<<gScan, 512>>>();
    k_scatter<<<gE, TB>>>(ei, E);

    // ---- layer 1 (F=3) ----
    k_spmm3<<<gN, TB>>>(0, 1, -1);
    k_spmm3<<<gN, TB>>>(1, 2, 0);
    k_spmm3<<<gN, TB>>>(2, 3, 1);
    k_gemm1<<<(NN + 31) / 32, 256>>>(W1, b1);
    k_bnapply<<<gBN, TB>>>(0, 0, g1, be1);

    // ---- layer 2 ----
    k_spmm128w<<<gW8, 256>>>(0, 1, -1);
    k_spmm128w<<<gW8, 256>>>(1, 2, 0);
    k_spmm128w<<<gW8, 256>>>(2, 3, 1);
    k_gemm_f16<<<NPB, 256, SMEM_GEMM>>>(b2, 0, 0, Wrep, brep, out);
    k_bnapply<<<gBN, TB>>>(1, 0, g2, be2);

    // ---- layer 3 ----
    k_spmm128w<<<gW8, 256>>>(0, 1, -1);
    k_spmm128w<<<gW8, 256>>>(1, 2, 0);
    k_spmm128w<<<gW8, 256>>>(2, 3, 1);
    k_gemm_f16<<<NPB, 256, SMEM_GEMM>>>(b3, 1, 1, Wrep, brep, out);
    k_bnapply<<<gBN, TB>>>(2, 1, g3, be3);

    // ---- layer 4: GEMM with fused L2-norm + head ----
    k_spmm128w<<<gW8, 256>>>(0, 1, -1);
    k_spmm128w<<<gW8, 256>>>(1, 2, 0);
    k_spmm128w<<<gW8, 256>>>(2, 3, 1);
    k_gemm_f16<<<NPB, 256, SMEM_GEMM>>>(b4, 2, -2, Wrep, brep, out);
}